// round 11
// baseline (speedup 1.0000x reference)
#include <cuda_runtime.h>
#include <cuda_bf16.h>
#include <cstdint>
#include <cstddef>

// Problem constants
#define N_NEWS 10000
#define N_INT  50000
#define N_ALL  60000
#define F_IN   768
#define H      256
#define OUTD   8
#define NNODE  70000          // [0,10000) r0-news, [10000,60000) r1-int, [60000,70000) r2-news
#define ETOT   1300000
#define NB_SCAN 69

// ---------------- device scratch ----------------
__device__ __nv_bfloat16 g_XSh[N_ALL * F_IN], g_XSl[N_ALL * F_IN];

// Activations as SPLIT bf16 (hi/lo), concatenated-K layout:
//   CN*[10000][768]: cols 0-255 X_news, 256-511 A0, 512-767 A2
//   CI*[50000][512]: cols 0-255 X_int,  256-511 A1
__device__ __nv_bfloat16 g_CN0h[N_NEWS * 768], g_CN0l[N_NEWS * 768];
__device__ __nv_bfloat16 g_CN1h[N_NEWS * 768], g_CN1l[N_NEWS * 768];
__device__ __nv_bfloat16 g_CI0h[N_INT * 512],  g_CI0l[N_INT * 512];
__device__ __nv_bfloat16 g_CI1h[N_INT * 512],  g_CI1l[N_INT * 512];

__device__ int   g_deg[NNODE];
__device__ float g_inv[NNODE];
__device__ int   g_off[NNODE + 1];
__device__ int   g_cur[NNODE];
__device__ int   g_srt[ETOT];
__device__ int   g_bsum[NB_SCAN];

// Split/transposed weights, [256 N][K] bf16, hi & lo, concatenated layout.
#define WOFF_ENCN 0
#define WOFF_ENCI 196608
#define WOFF_LN(l) (393216 + (l) * 327680)
#define WOFF_LI(l) (589824 + (l) * 327680)
#define WTOTAL 1048576
__device__ __nv_bfloat16 g_Bhi[WTOTAL];
__device__ __nv_bfloat16 g_Blo[WTOTAL];

// ================= helpers =================
__device__ __forceinline__ uint32_t smem_u32(const void* p) {
    uint32_t a;
    asm("{ .reg .u64 t; cvta.to.shared.u64 t, %1; cvt.u32.u64 %0, t; }" : "=r"(a) : "l"(p));
    return a;
}
__device__ __forceinline__ uint32_t pack_bf2(__nv_bfloat16 a, __nv_bfloat16 b) {
    return (uint32_t)__bfloat16_as_ushort(a) | ((uint32_t)__bfloat16_as_ushort(b) << 16);
}
__device__ __forceinline__ void ldm_x4(uint32_t& r0, uint32_t& r1, uint32_t& r2, uint32_t& r3,
                                       uint32_t addr) {
    asm volatile("ldmatrix.sync.aligned.m8n8.x4.shared.b16 {%0,%1,%2,%3}, [%4];"
                 : "=r"(r0), "=r"(r1), "=r"(r2), "=r"(r3) : "r"(addr));
}
__device__ __forceinline__ void mma_bf16(float* c, uint32_t a0, uint32_t a1, uint32_t a2,
                                         uint32_t a3, uint32_t b0, uint32_t b1) {
    asm volatile("mma.sync.aligned.m16n8k16.row.col.f32.bf16.bf16.f32 "
                 "{%0,%1,%2,%3}, {%4,%5,%6,%7}, {%8,%9}, {%0,%1,%2,%3};"
                 : "+f"(c[0]), "+f"(c[1]), "+f"(c[2]), "+f"(c[3])
                 : "r"(a0), "r"(a1), "r"(a2), "r"(a3), "r"(b0), "r"(b1));
}
__device__ __forceinline__ void cp16(uint32_t dst, const void* src) {
    asm volatile("cp.async.cg.shared.global [%0], [%1], 16;" :: "r"(dst), "l"(src));
}
__device__ __forceinline__ void cp16z(uint32_t dst, const void* src, int sz) {
    asm volatile("cp.async.cg.shared.global [%0], [%1], 16, %2;" :: "r"(dst), "l"(src), "r"(sz));
}
__device__ __forceinline__ void split_bf(float v, __nv_bfloat16& h, __nv_bfloat16& l) {
    h = __float2bfloat16(v);
    l = __float2bfloat16(v - __bfloat162float(h));
}

// ================= pipelined HMMA GEMM (3-term bf16 split) =================
// C[M,0:256 of ldc] = A[M][K] @ B[K,256]; A and B split bf16 hi/lo; B [256][K].
// Block 128x128 (grid.x=2 covers N=256), BK=32, 8 warps (4m x 2n), warp tile 32x64.
// Dyn SMEM per buf: Ah@0, Al@10240, Bh@20480, Bl@30720 (128 rows x 80 B each).
#define BUFSZ 40960
#define GSMEM (2 * BUFSZ)

__device__ __forceinline__ void gemm_ldA(uint32_t bufb,
                                         const __nv_bfloat16* __restrict__ Ahi,
                                         const __nv_bfloat16* __restrict__ Alo,
                                         int K, int M, int row0, int fRow, int fHalf, int k0) {
    const int r = row0 + fRow;
    const int sz = (r < M) ? 16 : 0;
    const int rc = (r < M) ? r : (M - 1);
    const size_t gb = (size_t)rc * K + k0 + fHalf * 16;
    const uint32_t d = bufb + (uint32_t)(fRow * 80 + fHalf * 32);
    cp16z(d,              Ahi + gb,     sz);
    cp16z(d + 16,         Ahi + gb + 8, sz);
    cp16z(d + 10240,      Alo + gb,     sz);
    cp16z(d + 10240 + 16, Alo + gb + 8, sz);
}
__device__ __forceinline__ void gemm_ldB(uint32_t bufb, const __nv_bfloat16* __restrict__ Bth,
                                         const __nv_bfloat16* __restrict__ Btl,
                                         int K, int col0, int fRow, int fHalf, int k0) {
    const size_t gb = (size_t)(col0 + fRow) * K + k0 + fHalf * 16;
    const uint32_t d = bufb + 20480 + (uint32_t)(fRow * 80 + fHalf * 32);
    cp16(d,              Bth + gb);
    cp16(d + 16,         Bth + gb + 8);
    cp16(d + 10240,      Btl + gb);
    cp16(d + 10240 + 16, Btl + gb + 8);
}

template <bool RELU>
__global__ __launch_bounds__(256, 2) void mma_gemm_kernel(
    const __nv_bfloat16* __restrict__ Ahi,
    const __nv_bfloat16* __restrict__ Alo,
    const __nv_bfloat16* __restrict__ Bth,
    const __nv_bfloat16* __restrict__ Btl,
    const float* __restrict__ bias,
    __nv_bfloat16* __restrict__ Ch,
    __nv_bfloat16* __restrict__ Cl,
    int ldc, int M, int K) {
    extern __shared__ char smem[];
    const uint32_t sb = smem_u32(smem);
    const int tid  = threadIdx.x;
    const int wid  = tid >> 5;
    const int lane = tid & 31;
    const int wm   = wid & 3;
    const int wn   = wid >> 2;
    const int row0 = blockIdx.y * 128;
    const int col0 = blockIdx.x * 128;
    const int fRow = tid >> 1;
    const int fHalf = tid & 1;

    float acc[2][8][4];
    #pragma unroll
    for (int i = 0; i < 2; i++)
        #pragma unroll
        for (int j = 0; j < 8; j++)
            #pragma unroll
            for (int q = 0; q < 4; q++) acc[i][j][q] = 0.f;

    const int nchunks = K >> 5;

    // per-warp smem fragment addresses (row-permuted for conflict-free ldmatrix)
    const uint32_t aRowOff =
        (uint32_t)(wm * 32 + ((lane >> 3) & 1) * 8 + (lane & 7)) * 80 + (lane >> 4) * 16;
    const uint32_t bRowBase =
        (uint32_t)(wn * 64 + ((lane >> 4) & 1) * 8 + (lane & 7)) * 80 + ((lane >> 3) & 1) * 16;

    // prologue: chunk 0 -> buf 0
    gemm_ldA(sb, Ahi, Alo, K, M, row0, fRow, fHalf, 0);
    gemm_ldB(sb, Bth, Btl, K, col0, fRow, fHalf, 0);
    asm volatile("cp.async.commit_group;" ::: "memory");
    asm volatile("cp.async.wait_group 0;" ::: "memory");
    __syncthreads();

    for (int c = 0; c < nchunks; c++) {
        const int b = c & 1;
        const bool nxt = (c + 1) < nchunks;
        if (nxt) {
            const int k0 = (c + 1) << 5;
            gemm_ldA(sb + (b ^ 1) * BUFSZ, Ahi, Alo, K, M, row0, fRow, fHalf, k0);
            gemm_ldB(sb + (b ^ 1) * BUFSZ, Bth, Btl, K, col0, fRow, fHalf, k0);
            asm volatile("cp.async.commit_group;" ::: "memory");
        }

        const uint32_t aHb = sb + b * BUFSZ;
        const uint32_t aLb = aHb + 10240;
        const uint32_t bHb = aHb + 20480;
        const uint32_t bLb = aHb + 30720;
        #pragma unroll
        for (int kk = 0; kk < 2; kk++) {
            const uint32_t kOff = kk * 32;
            // A fragments for this kk
            uint32_t ah[2][4], al[2][4];
            #pragma unroll
            for (int mt = 0; mt < 2; mt++) {
                const uint32_t roff = aRowOff + (uint32_t)(mt * 16) * 80 + kOff;
                ldm_x4(ah[mt][0], ah[mt][1], ah[mt][2], ah[mt][3], aHb + roff);
                ldm_x4(al[mt][0], al[mt][1], al[mt][2], al[mt][3], aLb + roff);
            }
            // software-pipelined B fragments: load ng+1 while doing MMAs of ng
            uint32_t bh[2][4], bl[2][4];
            {
                const uint32_t boff = bRowBase + kOff;   // ng = 0
                ldm_x4(bh[0][0], bh[0][1], bh[0][2], bh[0][3], bHb + boff);
                ldm_x4(bl[0][0], bl[0][1], bl[0][2], bl[0][3], bLb + boff);
            }
            #pragma unroll
            for (int ng = 0; ng < 4; ng++) {
                const int cb = ng & 1;
                if (ng < 3) {
                    const uint32_t boff = bRowBase + (uint32_t)((ng + 1) * 16) * 80 + kOff;
                    ldm_x4(bh[cb ^ 1][0], bh[cb ^ 1][1], bh[cb ^ 1][2], bh[cb ^ 1][3], bHb + boff);
                    ldm_x4(bl[cb ^ 1][0], bl[cb ^ 1][1], bl[cb ^ 1][2], bl[cb ^ 1][3], bLb + boff);
                }
                #pragma unroll
                for (int mt = 0; mt < 2; mt++) {
                    #pragma unroll
                    for (int h = 0; h < 2; h++) {
                        float* cc = acc[mt][ng * 2 + h];
                        mma_bf16(cc, ah[mt][0], ah[mt][1], ah[mt][2], ah[mt][3],
                                 bh[cb][2 * h], bh[cb][2 * h + 1]);
                        mma_bf16(cc, ah[mt][0], ah[mt][1], ah[mt][2], ah[mt][3],
                                 bl[cb][2 * h], bl[cb][2 * h + 1]);
                        mma_bf16(cc, al[mt][0], al[mt][1], al[mt][2], al[mt][3],
                                 bh[cb][2 * h], bh[cb][2 * h + 1]);
                    }
                }
            }
        }

        if (nxt) asm volatile("cp.async.wait_group 0;" ::: "memory");
        __syncthreads();
    }

    // ---- epilogue: bias + optional relu, split to bf16 hi/lo ----
    const int colBase = col0 + wn * 64 + (lane & 3) * 2;
    #pragma unroll
    for (int mt = 0; mt < 2; mt++) {
        #pragma unroll
        for (int half = 0; half < 2; half++) {
            const int r = row0 + wm * 32 + mt * 16 + (lane >> 2) + half * 8;
            if (r < M) {
                #pragma unroll
                for (int nt = 0; nt < 8; nt++) {
                    const int c = colBase + nt * 8;
                    float v0 = acc[mt][nt][2 * half];
                    float v1 = acc[mt][nt][2 * half + 1];
                    const float2 bb = *(const float2*)(bias + c);
                    v0 += bb.x; v1 += bb.y;
                    if (RELU) { v0 = fmaxf(v0, 0.f); v1 = fmaxf(v1, 0.f); }
                    __nv_bfloat16 h0, l0, h1, l1;
                    split_bf(v0, h0, l0);
                    split_bf(v1, h1, l1);
                    *(uint32_t*)(Ch + (size_t)r * ldc + c) = pack_bf2(h0, h1);
                    *(uint32_t*)(Cl + (size_t)r * ldc + c) = pack_bf2(l0, l1);
                }
            }
        }
    }
}

// ---------------- x pre-split: fp32 -> bf16 hi/lo, merged news+int ----------------
__global__ void xsplit_kernel(const float* __restrict__ xn, const float* __restrict__ xi,
                              __nv_bfloat16* __restrict__ Xh, __nv_bfloat16* __restrict__ Xl) {
    const int base = (blockIdx.x * blockDim.x + threadIdx.x) * 4;
    if (base >= N_ALL * F_IN) return;
    const float* src = (base < N_NEWS * F_IN) ? (xn + base) : (xi + (base - N_NEWS * F_IN));
    const float4 v = *(const float4*)src;
    __nv_bfloat16 hx, lx, hy, ly, hz, lz, hw, lw;
    split_bf(v.x, hx, lx); split_bf(v.y, hy, ly);
    split_bf(v.z, hz, lz); split_bf(v.w, hw, lw);
    uint2 hp, lp;
    hp.x = pack_bf2(hx, hy); hp.y = pack_bf2(hz, hw);
    lp.x = pack_bf2(lx, ly); lp.y = pack_bf2(lz, lw);
    *(uint2*)(Xh + base) = hp;
    *(uint2*)(Xl + base) = lp;
}

// ---------------- single-launch weight prep ----------------
__global__ void wprep_all_kernel(const float* __restrict__ Wn, const float* __restrict__ Wi,
                                 const float* __restrict__ W_rel, const float* __restrict__ W_root,
                                 __nv_bfloat16* __restrict__ Bhi, __nv_bfloat16* __restrict__ Blo) {
    int idx = blockIdx.x * blockDim.x + threadIdx.x;
    if (idx >= WTOTAL) return;
    const float* src;
    int base, Kdst, koff, s;
    if (idx < 196608) {
        base = WOFF_ENCN; Kdst = 768; koff = 0; s = idx; src = Wn;
    } else if (idx < 393216) {
        base = WOFF_ENCI; Kdst = 768; koff = 0; s = idx - 196608; src = Wi;
    } else {
        int t = idx - 393216;
        const int l = (t >= 327680) ? 1 : 0;
        if (l) t -= 327680;
        if (t < 196608) {
            base = WOFF_LN(l); Kdst = 768;
            const int j = t >> 16;
            s = t & 65535;
            koff = j * 256;
            src = (j == 0) ? (W_root + l * 65536)
                           : (W_rel + (l * 3 + ((j == 1) ? 0 : 2)) * 65536);
        } else {
            t -= 196608;
            base = WOFF_LI(l); Kdst = 512;
            const int j = t >> 16;
            s = t & 65535;
            koff = j * 256;
            src = (j == 0) ? (W_root + l * 65536) : (W_rel + (l * 3 + 1) * 65536);
        }
    }
    const int k = s >> 8;
    const int n = s & 255;
    const float v = src[k * 256 + n];
    __nv_bfloat16 h, l2;
    split_bf(v, h, l2);
    const size_t d = (size_t)base + (size_t)n * Kdst + koff + k;
    Bhi[d] = h;
    Blo[d] = l2;
}

// ---------------- CSR build ----------------
__global__ void deg_all_kernel(const int* __restrict__ d0, const int* __restrict__ d1,
                               const int* __restrict__ d2, int E0, int E01, int ET,
                               int* __restrict__ deg) {
    int e = blockIdx.x * blockDim.x + threadIdx.x;
    if (e >= ET) return;
    if (e < E0)       atomicAdd(&deg[d0[e]], 1);
    else if (e < E01) atomicAdd(&deg[10000 + d1[e - E0]], 1);
    else              atomicAdd(&deg[60000 + d2[e - E01]], 1);
}

__global__ __launch_bounds__(256) void scan_p1(const int* __restrict__ deg,
                                               int* __restrict__ off,
                                               float* __restrict__ inv,
                                               int* __restrict__ bsum) {
    __shared__ int ws[8];
    const int t = (int)threadIdx.x;
    const int base = (blockIdx.x * 256 + t) * 4;
    int4 d = make_int4(0, 0, 0, 0);
    if (base < NNODE) {
        d = *(const int4*)(deg + base);
        *(float4*)(inv + base) = make_float4(
            d.x > 0 ? 1.f / (float)d.x : 0.f, d.y > 0 ? 1.f / (float)d.y : 0.f,
            d.z > 0 ? 1.f / (float)d.z : 0.f, d.w > 0 ? 1.f / (float)d.w : 0.f);
    }
    const int local = d.x + d.y + d.z + d.w;
    const int lane = t & 31, w = t >> 5;
    int v = local;
    #pragma unroll
    for (int s = 1; s < 32; s <<= 1) {
        int u = __shfl_up_sync(0xFFFFFFFFu, v, s);
        if (lane >= s) v += u;
    }
    if (lane == 31) ws[w] = v;
    __syncthreads();
    if (t == 0) {
        int run = 0;
        #pragma unroll
        for (int i = 0; i < 8; i++) { int x = ws[i]; ws[i] = run; run += x; }
        bsum[blockIdx.x] = run;
    }
    __syncthreads();
    const int excl = (v - local) + ws[w];
    if (base < NNODE) {
        off[base]     = excl;
        off[base + 1] = excl + d.x;
        off[base + 2] = excl + d.x + d.y;
        off[base + 3] = excl + d.x + d.y + d.z;
    }
}

__global__ __launch_bounds__(128) void scan_p2(int* __restrict__ bsum,
                                               int* __restrict__ off, int ET) {
    __shared__ int sh[128];
    const int t = (int)threadIdx.x;
    const int v = (t < NB_SCAN) ? bsum[t] : 0;
    sh[t] = v;
    __syncthreads();
    #pragma unroll
    for (int s = 1; s < 128; s <<= 1) {
        int u = (t >= s) ? sh[t - s] : 0;
        __syncthreads();
        sh[t] += u;
        __syncthreads();
    }
    if (t < NB_SCAN) bsum[t] = sh[t] - v;
    if (t == 0) off[NNODE] = ET;
}

__global__ __launch_bounds__(256) void scan_p3(int* __restrict__ off, int* __restrict__ cur,
                                               const int* __restrict__ bsum) {
    const int base = (blockIdx.x * 256 + (int)threadIdx.x) * 4;
    if (base < NNODE) {
        const int bs = bsum[blockIdx.x];
        int4 o = *(int4*)(off + base);
        o.x += bs; o.y += bs; o.z += bs; o.w += bs;
        *(int4*)(off + base) = o;
        *(int4*)(cur + base) = o;
    }
}

__global__ void fill_all_kernel(const int* __restrict__ s0, const int* __restrict__ d0,
                                const int* __restrict__ s1, const int* __restrict__ d1,
                                const int* __restrict__ s2, const int* __restrict__ d2,
                                int E0, int E01, int ET,
                                int* __restrict__ cur, int* __restrict__ srt) {
    int e = blockIdx.x * blockDim.x + threadIdx.x;
    if (e >= ET) return;
    int di, sv;
    if (e < E0)       { di = d0[e];               sv = s0[e]; }
    else if (e < E01) { di = 10000 + d1[e - E0];  sv = s1[e - E0]; }
    else              { di = 60000 + d2[e - E01]; sv = s2[e - E01] + 10000; }
    int p = atomicAdd(&cur[di], 1);
    srt[p] = sv;
}

// ---------------- merged mean aggregation (split bf16 in/out, 2x unroll) ----------
__device__ __forceinline__ void acc8(float* a, uint4 v) {
    const __nv_bfloat162* p = (const __nv_bfloat162*)&v;
    #pragma unroll
    for (int i = 0; i < 4; i++) {
        float2 f = __bfloat1622float2(p[i]);
        a[2 * i] += f.x;
        a[2 * i + 1] += f.y;
    }
}
__device__ __forceinline__ void src_ptrs(int src, const __nv_bfloat16* CNh, const __nv_bfloat16* CNl,
                                         const __nv_bfloat16* CIh, const __nv_bfloat16* CIl,
                                         const __nv_bfloat16*& rh, const __nv_bfloat16*& rl) {
    if (src < 10000) { rh = CNh + (size_t)src * 768; rl = CNl + (size_t)src * 768; }
    else             { rh = CIh + (size_t)(src - 10000) * 512; rl = CIl + (size_t)(src - 10000) * 512; }
}

__global__ void agg_all_kernel(__nv_bfloat16* __restrict__ CNh, __nv_bfloat16* __restrict__ CNl,
                               __nv_bfloat16* __restrict__ CIh, __nv_bfloat16* __restrict__ CIl,
                               const int* __restrict__ off, const int* __restrict__ srt,
                               const float* __restrict__ inv) {
    const int gw   = (int)((blockIdx.x * blockDim.x + threadIdx.x) >> 5);
    const int lane = threadIdx.x & 31;
    if (gw >= NNODE) return;
    __nv_bfloat16 *oh, *ol;
    if (gw < 10000) {
        oh = CNh + (size_t)gw * 768 + 256; ol = CNl + (size_t)gw * 768 + 256;
    } else if (gw < 60000) {
        const int i = gw - 10000;
        oh = CIh + (size_t)i * 512 + 256; ol = CIl + (size_t)i * 512 + 256;
    } else {
        const int i = gw - 60000;
        oh = CNh + (size_t)i * 768 + 512; ol = CNl + (size_t)i * 768 + 512;
    }
    const int e0 = off[gw], e1 = off[gw + 1];
    const int co = lane * 8;
    float a[8];
    #pragma unroll
    for (int i = 0; i < 8; i++) a[i] = 0.f;
    int e = e0;
    for (; e + 2 <= e1; e += 2) {
        const int sA = __ldg(&srt[e]);
        const int sB = __ldg(&srt[e + 1]);
        const __nv_bfloat16 *rhA, *rlA, *rhB, *rlB;
        src_ptrs(sA, CNh, CNl, CIh, CIl, rhA, rlA);
        src_ptrs(sB, CNh, CNl, CIh, CIl, rhB, rlB);
        const uint4 h0 = __ldg((const uint4*)(rhA + co));
        const uint4 l0 = __ldg((const uint4*)(rlA + co));
        const uint4 h1 = __ldg((const uint4*)(rhB + co));
        const uint4 l1 = __ldg((const uint4*)(rlB + co));
        acc8(a, h0); acc8(a, l0);
        acc8(a, h1); acc8(a, l1);
    }
    if (e < e1) {
        const int sA = __ldg(&srt[e]);
        const __nv_bfloat16 *rhA, *rlA;
        src_ptrs(sA, CNh, CNl, CIh, CIl, rhA, rlA);
        acc8(a, __ldg((const uint4*)(rhA + co)));
        acc8(a, __ldg((const uint4*)(rlA + co)));
    }
    const float d = inv[gw];
    uint4 ho, lo_;
    uint32_t* hp = (uint32_t*)&ho;
    uint32_t* lp = (uint32_t*)&lo_;
    #pragma unroll
    for (int i = 0; i < 4; i++) {
        float v0 = a[2 * i] * d, v1 = a[2 * i + 1] * d;
        __nv_bfloat16 h0, l0, h1, l1;
        split_bf(v0, h0, l0);
        split_bf(v1, h1, l1);
        hp[i] = pack_bf2(h0, h1);
        lp[i] = pack_bf2(l0, l1);
    }
    *(uint4*)(oh + co) = ho;
    *(uint4*)(ol + co) = lo_;
}

// ---------------- final projection ----------------
__global__ __launch_bounds__(256) void out_proj_kernel(
    const __nv_bfloat16* __restrict__ Xh, const __nv_bfloat16* __restrict__ Xl,
    const float* __restrict__ W, const float* __restrict__ b,
    float* __restrict__ out) {
    __shared__ float sW[H * OUTD];
    for (int i = threadIdx.x; i < H * OUTD; i += 256) sW[i] = W[i];
    __syncthreads();
    const int i = blockIdx.x * 32 + ((int)threadIdx.x >> 3);
    const int o = threadIdx.x & 7;
    if (i >= N_NEWS) return;
    float s = b[o];
    const __nv_bfloat16* xh = Xh + (size_t)i * 768;
    const __nv_bfloat16* xl = Xl + (size_t)i * 768;
    #pragma unroll 8
    for (int j = 0; j < H; j++) {
        float x = __bfloat162float(xh[j]) + __bfloat162float(xl[j]);
        s += x * sW[j * OUTD + o];
    }
    out[i * OUTD + o] = s;
}

// ---------------- launch ----------------
extern "C" void kernel_launch(void* const* d_in, const int* in_sizes, int n_in,
                              void* d_out, int out_size) {
    const float* x_news = (const float*)d_in[0];
    const float* x_int  = (const float*)d_in[1];
    const float* Wn     = (const float*)d_in[2];
    const float* bn     = (const float*)d_in[3];
    const float* Wi     = (const float*)d_in[4];
    const float* bi     = (const float*)d_in[5];
    const float* W_rel  = (const float*)d_in[6];
    const float* W_root = (const float*)d_in[7];
    const float* conv_b = (const float*)d_in[8];
    const float* out_W  = (const float*)d_in[9];
    const float* out_b  = (const float*)d_in[10];
    const int* e0s = (const int*)d_in[11];
    const int* e0d = (const int*)d_in[12];
    const int* e1s = (const int*)d_in[13];
    const int* e1d = (const int*)d_in[14];
    const int* e2s = (const int*)d_in[15];
    const int* e2d = (const int*)d_in[16];
    const int E0 = in_sizes[11], E1 = in_sizes[13], E2 = in_sizes[15];
    const int E01 = E0 + E1, ET = E0 + E1 + E2;
    float* out = (float*)d_out;

    __nv_bfloat16 *XSh, *XSl, *CN0h, *CN0l, *CN1h, *CN1l, *CI0h, *CI0l, *CI1h, *CI1l, *Bhi, *Blo;
    float *inv;
    int *deg, *off, *cur, *srt, *bsum;
    cudaGetSymbolAddress((void**)&XSh, g_XSh);
    cudaGetSymbolAddress((void**)&XSl, g_XSl);
    cudaGetSymbolAddress((void**)&CN0h, g_CN0h);
    cudaGetSymbolAddress((void**)&CN0l, g_CN0l);
    cudaGetSymbolAddress((void**)&CN1h, g_CN1h);
    cudaGetSymbolAddress((void**)&CN1l, g_CN1l);
    cudaGetSymbolAddress((void**)&CI0h, g_CI0h);
    cudaGetSymbolAddress((void**)&CI0l, g_CI0l);
    cudaGetSymbolAddress((void**)&CI1h, g_CI1h);
    cudaGetSymbolAddress((void**)&CI1l, g_CI1l);
    cudaGetSymbolAddress((void**)&deg, g_deg);
    cudaGetSymbolAddress((void**)&inv, g_inv);
    cudaGetSymbolAddress((void**)&off, g_off);
    cudaGetSymbolAddress((void**)&cur, g_cur);
    cudaGetSymbolAddress((void**)&srt, g_srt);
    cudaGetSymbolAddress((void**)&bsum, g_bsum);
    cudaGetSymbolAddress((void**)&Bhi, g_Bhi);
    cudaGetSymbolAddress((void**)&Blo, g_Blo);

    cudaFuncSetAttribute((const void*)mma_gemm_kernel<false>,
                         cudaFuncAttributeMaxDynamicSharedMemorySize, GSMEM);
    cudaFuncSetAttribute((const void*)mma_gemm_kernel<true>,
                         cudaFuncAttributeMaxDynamicSharedMemorySize, GSMEM);

    // launch order keeps the 4th kernel (ncu capture slot) = big encodeI GEMM
    wprep_all_kernel<<<(WTOTAL + 255) / 256, 256>>>(Wn, Wi, W_rel, W_root, Bhi, Blo);           // 0
    xsplit_kernel<<<(N_ALL * F_IN / 4 + 255) / 256, 256>>>(x_news, x_int, XSh, XSl);            // 1
    mma_gemm_kernel<false><<<dim3(2, (N_NEWS + 127) / 128), 256, GSMEM>>>(                      // 2
        XSh, XSl, Bhi + WOFF_ENCN, Blo + WOFF_ENCN, bn, CN0h, CN0l, 768, N_NEWS, F_IN);
    mma_gemm_kernel<false><<<dim3(2, (N_INT + 127) / 128), 256, GSMEM>>>(                       // 3 <- profiled
        XSh + (size_t)N_NEWS * F_IN, XSl + (size_t)N_NEWS * F_IN,
        Bhi + WOFF_ENCI, Blo + WOFF_ENCI, bi, CI0h, CI0l, 512, N_INT, F_IN);

    // CSR build
    cudaMemsetAsync(deg, 0, NNODE * sizeof(int));
    deg_all_kernel<<<(ET + 255) / 256, 256>>>(e0d, e1d, e2d, E0, E01, ET, deg);
    scan_p1<<<NB_SCAN, 256>>>(deg, off, inv, bsum);
    scan_p2<<<1, 128>>>(bsum, off, ET);
    scan_p3<<<NB_SCAN, 256>>>(off, cur, bsum);
    fill_all_kernel<<<(ET + 255) / 256, 256>>>(e0s, e0d, e1s, e1d, e2s, e2d,
                                               E0, E01, ET, cur, srt);

    __nv_bfloat16* CNhs[2] = {CN0h, CN1h};
    __nv_bfloat16* CNls[2] = {CN0l, CN1l};
    __nv_bfloat16* CIhs[2] = {CI0h, CI1h};
    __nv_bfloat16* CIls[2] = {CI0l, CI1l};
    for (int l = 0; l < 2; l++) {
        __nv_bfloat16 *CNch = CNhs[l & 1], *CNcl = CNls[l & 1];
        __nv_bfloat16 *CIch = CIhs[l & 1], *CIcl = CIls[l & 1];
        __nv_bfloat16 *CNnh = CNhs[(l + 1) & 1], *CNnl = CNls[(l + 1) & 1];
        __nv_bfloat16 *CInh = CIhs[(l + 1) & 1], *CInl = CIls[(l + 1) & 1];

        agg_all_kernel<<<(NNODE * 32 + 255) / 256, 256>>>(CNch, CNcl, CIch, CIcl, off, srt, inv);

        mma_gemm_kernel<true><<<dim3(2, (N_NEWS + 127) / 128), 256, GSMEM>>>(
            CNch, CNcl, Bhi + WOFF_LN(l), Blo + WOFF_LN(l), conv_b + (size_t)l * H,
            CNnh, CNnl, 768, N_NEWS, 768);
        mma_gemm_kernel<true><<<dim3(2, (N_INT + 127) / 128), 256, GSMEM>>>(
            CIch, CIcl, Bhi + WOFF_LI(l), Blo + WOFF_LI(l), conv_b + (size_t)l * H,
            CInh, CInl, 512, N_INT, 512);
    }

    out_proj_kernel<<<(N_NEWS + 31) / 32, 256>>>(CN0h, CN0l, out_W, out_b, out);
}

// round 12
// speedup vs baseline: 1.4997x; 1.4997x over previous
#include <cuda_runtime.h>
#include <cuda_bf16.h>
#include <cstdint>
#include <cstddef>

// Problem constants
#define N_NEWS 10000
#define N_INT  50000
#define N_ALL  60000
#define F_IN   768
#define H      256
#define OUTD   8
#define NNODE  70000          // [0,10000) r0-news, [10000,60000) r1-int, [60000,70000) r2-news
#define ETOT   1300000
#define NB_SCAN 69

// ---------------- device scratch ----------------
__device__ __nv_bfloat16 g_XSh[N_ALL * F_IN], g_XSl[N_ALL * F_IN];

// Activations as SPLIT bf16 (hi/lo), concatenated-K layout:
//   CN*[10000][768]: cols 0-255 X_news, 256-511 A0, 512-767 A2
//   CI*[50000][512]: cols 0-255 X_int,  256-511 A1
__device__ __nv_bfloat16 g_CN0h[N_NEWS * 768], g_CN0l[N_NEWS * 768];
__device__ __nv_bfloat16 g_CN1h[N_NEWS * 768], g_CN1l[N_NEWS * 768];
__device__ __nv_bfloat16 g_CI0h[N_INT * 512],  g_CI0l[N_INT * 512];
__device__ __nv_bfloat16 g_CI1h[N_INT * 512],  g_CI1l[N_INT * 512];

__device__ int   g_deg[NNODE];
__device__ float g_inv[NNODE];
__device__ int   g_off[NNODE + 1];
__device__ int   g_cur[NNODE];
__device__ int   g_srt[ETOT];
__device__ int   g_bsum[NB_SCAN];

// Split/transposed weights, [256 N][K] bf16, hi & lo, concatenated layout.
#define WOFF_ENCN 0
#define WOFF_ENCI 196608
#define WOFF_LN(l) (393216 + (l) * 327680)
#define WOFF_LI(l) (589824 + (l) * 327680)
#define WTOTAL 1048576
__device__ __nv_bfloat16 g_Bhi[WTOTAL];
__device__ __nv_bfloat16 g_Blo[WTOTAL];

// ================= helpers =================
__device__ __forceinline__ uint32_t smem_u32(const void* p) {
    uint32_t a;
    asm("{ .reg .u64 t; cvta.to.shared.u64 t, %1; cvt.u32.u64 %0, t; }" : "=r"(a) : "l"(p));
    return a;
}
__device__ __forceinline__ uint32_t pack_bf2(__nv_bfloat16 a, __nv_bfloat16 b) {
    return (uint32_t)__bfloat16_as_ushort(a) | ((uint32_t)__bfloat16_as_ushort(b) << 16);
}
__device__ __forceinline__ void ldm_x4(uint32_t& r0, uint32_t& r1, uint32_t& r2, uint32_t& r3,
                                       uint32_t addr) {
    asm volatile("ldmatrix.sync.aligned.m8n8.x4.shared.b16 {%0,%1,%2,%3}, [%4];"
                 : "=r"(r0), "=r"(r1), "=r"(r2), "=r"(r3) : "r"(addr));
}
__device__ __forceinline__ void mma_bf16(float* c, uint32_t a0, uint32_t a1, uint32_t a2,
                                         uint32_t a3, uint32_t b0, uint32_t b1) {
    asm volatile("mma.sync.aligned.m16n8k16.row.col.f32.bf16.bf16.f32 "
                 "{%0,%1,%2,%3}, {%4,%5,%6,%7}, {%8,%9}, {%0,%1,%2,%3};"
                 : "+f"(c[0]), "+f"(c[1]), "+f"(c[2]), "+f"(c[3])
                 : "r"(a0), "r"(a1), "r"(a2), "r"(a3), "r"(b0), "r"(b1));
}
__device__ __forceinline__ void cp16(uint32_t dst, const void* src) {
    asm volatile("cp.async.cg.shared.global [%0], [%1], 16;" :: "r"(dst), "l"(src));
}
__device__ __forceinline__ void cp16z(uint32_t dst, const void* src, int sz) {
    asm volatile("cp.async.cg.shared.global [%0], [%1], 16, %2;" :: "r"(dst), "l"(src), "r"(sz));
}
__device__ __forceinline__ void split_bf(float v, __nv_bfloat16& h, __nv_bfloat16& l) {
    h = __float2bfloat16(v);
    l = __float2bfloat16(v - __bfloat162float(h));
}

// ================= pipelined HMMA GEMM (3-term bf16 split) =================
// C[M,0:256 of ldc] = A[M][K] @ B[K,256]; A and B split bf16 hi/lo; B [256][K].
// Block 128x128 (grid.x=2 covers N=256), BK=32, 8 warps (4m x 2n), warp tile 32x64.
// Dyn SMEM per buf: Ah@0, Al@10240, Bh@20480, Bl@30720 (128 rows x 80 B each).
#define BUFSZ 40960
#define GSMEM (2 * BUFSZ)

__device__ __forceinline__ void gemm_ldA(uint32_t bufb,
                                         const __nv_bfloat16* __restrict__ Ahi,
                                         const __nv_bfloat16* __restrict__ Alo,
                                         int K, int M, int row0, int fRow, int fHalf, int k0) {
    const int r = row0 + fRow;
    const int sz = (r < M) ? 16 : 0;
    const int rc = (r < M) ? r : (M - 1);
    const size_t gb = (size_t)rc * K + k0 + fHalf * 16;
    const uint32_t d = bufb + (uint32_t)(fRow * 80 + fHalf * 32);
    cp16z(d,              Ahi + gb,     sz);
    cp16z(d + 16,         Ahi + gb + 8, sz);
    cp16z(d + 10240,      Alo + gb,     sz);
    cp16z(d + 10240 + 16, Alo + gb + 8, sz);
}
__device__ __forceinline__ void gemm_ldB(uint32_t bufb, const __nv_bfloat16* __restrict__ Bth,
                                         const __nv_bfloat16* __restrict__ Btl,
                                         int K, int col0, int fRow, int fHalf, int k0) {
    const size_t gb = (size_t)(col0 + fRow) * K + k0 + fHalf * 16;
    const uint32_t d = bufb + 20480 + (uint32_t)(fRow * 80 + fHalf * 32);
    cp16(d,              Bth + gb);
    cp16(d + 16,         Bth + gb + 8);
    cp16(d + 10240,      Btl + gb);
    cp16(d + 10240 + 16, Btl + gb + 8);
}

template <bool RELU>
__global__ __launch_bounds__(256, 2) void mma_gemm_kernel(
    const __nv_bfloat16* __restrict__ Ahi,
    const __nv_bfloat16* __restrict__ Alo,
    const __nv_bfloat16* __restrict__ Bth,
    const __nv_bfloat16* __restrict__ Btl,
    const float* __restrict__ bias,
    __nv_bfloat16* __restrict__ Ch,
    __nv_bfloat16* __restrict__ Cl,
    int ldc, int M, int K) {
    extern __shared__ char smem[];
    const uint32_t sb = smem_u32(smem);
    const int tid  = threadIdx.x;
    const int wid  = tid >> 5;
    const int lane = tid & 31;
    const int wm   = wid & 3;
    const int wn   = wid >> 2;
    const int row0 = blockIdx.y * 128;
    const int col0 = blockIdx.x * 128;
    const int fRow = tid >> 1;
    const int fHalf = tid & 1;

    float acc[2][8][4];
    #pragma unroll
    for (int i = 0; i < 2; i++)
        #pragma unroll
        for (int j = 0; j < 8; j++)
            #pragma unroll
            for (int q = 0; q < 4; q++) acc[i][j][q] = 0.f;

    const int nchunks = K >> 5;

    // per-warp smem fragment base addresses (row-permuted, conflict-free ldmatrix)
    const uint32_t aRowOff =
        (uint32_t)(wm * 32 + ((lane >> 3) & 1) * 8 + (lane & 7)) * 80 + (lane >> 4) * 16;
    const uint32_t bRowBase =
        (uint32_t)(wn * 64 + ((lane >> 4) & 1) * 8 + (lane & 7)) * 80 + ((lane >> 3) & 1) * 16;

    // prologue: chunk 0 -> buf 0
    gemm_ldA(sb, Ahi, Alo, K, M, row0, fRow, fHalf, 0);
    gemm_ldB(sb, Bth, Btl, K, col0, fRow, fHalf, 0);
    asm volatile("cp.async.commit_group;" ::: "memory");
    asm volatile("cp.async.wait_group 0;" ::: "memory");
    __syncthreads();

    for (int c = 0; c < nchunks; c++) {
        const int b = c & 1;
        const bool nxt = (c + 1) < nchunks;
        if (nxt) {
            const int k0 = (c + 1) << 5;
            gemm_ldA(sb + (b ^ 1) * BUFSZ, Ahi, Alo, K, M, row0, fRow, fHalf, k0);
            gemm_ldB(sb + (b ^ 1) * BUFSZ, Bth, Btl, K, col0, fRow, fHalf, k0);
            asm volatile("cp.async.commit_group;" ::: "memory");
        }

        const uint32_t aHb = sb + b * BUFSZ;
        const uint32_t aLb = aHb + 10240;
        const uint32_t bHb = aHb + 20480;
        const uint32_t bLb = aHb + 30720;
        #pragma unroll
        for (int kk = 0; kk < 2; kk++) {
            const uint32_t kOff = kk * 32;
            // A fragments (hi & lo) for this kk
            uint32_t ah[2][4], al[2][4];
            #pragma unroll
            for (int mt = 0; mt < 2; mt++) {
                const uint32_t roff = aRowOff + (uint32_t)(mt * 16) * 80 + kOff;
                ldm_x4(ah[mt][0], ah[mt][1], ah[mt][2], ah[mt][3], aHb + roff);
                ldm_x4(al[mt][0], al[mt][1], al[mt][2], al[mt][3], aLb + roff);
            }
            #pragma unroll
            for (int ng = 0; ng < 4; ng++) {
                const uint32_t boff = bRowBase + (uint32_t)(ng * 16) * 80 + kOff;
                uint32_t bh[4], bl[4];
                ldm_x4(bh[0], bh[1], bh[2], bh[3], bHb + boff);
                ldm_x4(bl[0], bl[1], bl[2], bl[3], bLb + boff);
                // term-major order: each acc register is revisited only every
                // 4 MMAs (mt x h), so HMMA RAW chains overlap instead of
                // serializing 3 deep per accumulator.
                #pragma unroll
                for (int mt = 0; mt < 2; mt++)
                    #pragma unroll
                    for (int h = 0; h < 2; h++)
                        mma_bf16(acc[mt][ng * 2 + h], ah[mt][0], ah[mt][1], ah[mt][2], ah[mt][3],
                                 bh[2 * h], bh[2 * h + 1]);
                #pragma unroll
                for (int mt = 0; mt < 2; mt++)
                    #pragma unroll
                    for (int h = 0; h < 2; h++)
                        mma_bf16(acc[mt][ng * 2 + h], ah[mt][0], ah[mt][1], ah[mt][2], ah[mt][3],
                                 bl[2 * h], bl[2 * h + 1]);
                #pragma unroll
                for (int mt = 0; mt < 2; mt++)
                    #pragma unroll
                    for (int h = 0; h < 2; h++)
                        mma_bf16(acc[mt][ng * 2 + h], al[mt][0], al[mt][1], al[mt][2], al[mt][3],
                                 bh[2 * h], bh[2 * h + 1]);
            }
        }

        if (nxt) asm volatile("cp.async.wait_group 0;" ::: "memory");
        __syncthreads();
    }

    // ---- epilogue: bias + optional relu, split to bf16 hi/lo ----
    const int colBase = col0 + wn * 64 + (lane & 3) * 2;
    #pragma unroll
    for (int mt = 0; mt < 2; mt++) {
        #pragma unroll
        for (int half = 0; half < 2; half++) {
            const int r = row0 + wm * 32 + mt * 16 + (lane >> 2) + half * 8;
            if (r < M) {
                #pragma unroll
                for (int nt = 0; nt < 8; nt++) {
                    const int c = colBase + nt * 8;
                    float v0 = acc[mt][nt][2 * half];
                    float v1 = acc[mt][nt][2 * half + 1];
                    const float2 bb = *(const float2*)(bias + c);
                    v0 += bb.x; v1 += bb.y;
                    if (RELU) { v0 = fmaxf(v0, 0.f); v1 = fmaxf(v1, 0.f); }
                    __nv_bfloat16 h0, l0, h1, l1;
                    split_bf(v0, h0, l0);
                    split_bf(v1, h1, l1);
                    *(uint32_t*)(Ch + (size_t)r * ldc + c) = pack_bf2(h0, h1);
                    *(uint32_t*)(Cl + (size_t)r * ldc + c) = pack_bf2(l0, l1);
                }
            }
        }
    }
}

// ---------------- x pre-split: fp32 -> bf16 hi/lo, merged news+int ----------------
__global__ void xsplit_kernel(const float* __restrict__ xn, const float* __restrict__ xi,
                              __nv_bfloat16* __restrict__ Xh, __nv_bfloat16* __restrict__ Xl) {
    const int base = (blockIdx.x * blockDim.x + threadIdx.x) * 4;
    if (base >= N_ALL * F_IN) return;
    const float* src = (base < N_NEWS * F_IN) ? (xn + base) : (xi + (base - N_NEWS * F_IN));
    const float4 v = *(const float4*)src;
    __nv_bfloat16 hx, lx, hy, ly, hz, lz, hw, lw;
    split_bf(v.x, hx, lx); split_bf(v.y, hy, ly);
    split_bf(v.z, hz, lz); split_bf(v.w, hw, lw);
    uint2 hp, lp;
    hp.x = pack_bf2(hx, hy); hp.y = pack_bf2(hz, hw);
    lp.x = pack_bf2(lx, ly); lp.y = pack_bf2(lz, lw);
    *(uint2*)(Xh + base) = hp;
    *(uint2*)(Xl + base) = lp;
}

// ---------------- single-launch weight prep ----------------
__global__ void wprep_all_kernel(const float* __restrict__ Wn, const float* __restrict__ Wi,
                                 const float* __restrict__ W_rel, const float* __restrict__ W_root,
                                 __nv_bfloat16* __restrict__ Bhi, __nv_bfloat16* __restrict__ Blo) {
    int idx = blockIdx.x * blockDim.x + threadIdx.x;
    if (idx >= WTOTAL) return;
    const float* src;
    int base, Kdst, koff, s;
    if (idx < 196608) {
        base = WOFF_ENCN; Kdst = 768; koff = 0; s = idx; src = Wn;
    } else if (idx < 393216) {
        base = WOFF_ENCI; Kdst = 768; koff = 0; s = idx - 196608; src = Wi;
    } else {
        int t = idx - 393216;
        const int l = (t >= 327680) ? 1 : 0;
        if (l) t -= 327680;
        if (t < 196608) {
            base = WOFF_LN(l); Kdst = 768;
            const int j = t >> 16;
            s = t & 65535;
            koff = j * 256;
            src = (j == 0) ? (W_root + l * 65536)
                           : (W_rel + (l * 3 + ((j == 1) ? 0 : 2)) * 65536);
        } else {
            t -= 196608;
            base = WOFF_LI(l); Kdst = 512;
            const int j = t >> 16;
            s = t & 65535;
            koff = j * 256;
            src = (j == 0) ? (W_root + l * 65536) : (W_rel + (l * 3 + 1) * 65536);
        }
    }
    const int k = s >> 8;
    const int n = s & 255;
    const float v = src[k * 256 + n];
    __nv_bfloat16 h, l2;
    split_bf(v, h, l2);
    const size_t d = (size_t)base + (size_t)n * Kdst + koff + k;
    Bhi[d] = h;
    Blo[d] = l2;
}

// ---------------- CSR build ----------------
__global__ void deg_all_kernel(const int* __restrict__ d0, const int* __restrict__ d1,
                               const int* __restrict__ d2, int E0, int E01, int ET,
                               int* __restrict__ deg) {
    int e = blockIdx.x * blockDim.x + threadIdx.x;
    if (e >= ET) return;
    if (e < E0)       atomicAdd(&deg[d0[e]], 1);
    else if (e < E01) atomicAdd(&deg[10000 + d1[e - E0]], 1);
    else              atomicAdd(&deg[60000 + d2[e - E01]], 1);
}

__global__ __launch_bounds__(256) void scan_p1(const int* __restrict__ deg,
                                               int* __restrict__ off,
                                               float* __restrict__ inv,
                                               int* __restrict__ bsum) {
    __shared__ int ws[8];
    const int t = (int)threadIdx.x;
    const int base = (blockIdx.x * 256 + t) * 4;
    int4 d = make_int4(0, 0, 0, 0);
    if (base < NNODE) {
        d = *(const int4*)(deg + base);
        *(float4*)(inv + base) = make_float4(
            d.x > 0 ? 1.f / (float)d.x : 0.f, d.y > 0 ? 1.f / (float)d.y : 0.f,
            d.z > 0 ? 1.f / (float)d.z : 0.f, d.w > 0 ? 1.f / (float)d.w : 0.f);
    }
    const int local = d.x + d.y + d.z + d.w;
    const int lane = t & 31, w = t >> 5;
    int v = local;
    #pragma unroll
    for (int s = 1; s < 32; s <<= 1) {
        int u = __shfl_up_sync(0xFFFFFFFFu, v, s);
        if (lane >= s) v += u;
    }
    if (lane == 31) ws[w] = v;
    __syncthreads();
    if (t == 0) {
        int run = 0;
        #pragma unroll
        for (int i = 0; i < 8; i++) { int x = ws[i]; ws[i] = run; run += x; }
        bsum[blockIdx.x] = run;
    }
    __syncthreads();
    const int excl = (v - local) + ws[w];
    if (base < NNODE) {
        off[base]     = excl;
        off[base + 1] = excl + d.x;
        off[base + 2] = excl + d.x + d.y;
        off[base + 3] = excl + d.x + d.y + d.z;
    }
}

__global__ __launch_bounds__(128) void scan_p2(int* __restrict__ bsum,
                                               int* __restrict__ off, int ET) {
    __shared__ int sh[128];
    const int t = (int)threadIdx.x;
    const int v = (t < NB_SCAN) ? bsum[t] : 0;
    sh[t] = v;
    __syncthreads();
    #pragma unroll
    for (int s = 1; s < 128; s <<= 1) {
        int u = (t >= s) ? sh[t - s] : 0;
        __syncthreads();
        sh[t] += u;
        __syncthreads();
    }
    if (t < NB_SCAN) bsum[t] = sh[t] - v;
    if (t == 0) off[NNODE] = ET;
}

__global__ __launch_bounds__(256) void scan_p3(int* __restrict__ off, int* __restrict__ cur,
                                               const int* __restrict__ bsum) {
    const int base = (blockIdx.x * 256 + (int)threadIdx.x) * 4;
    if (base < NNODE) {
        const int bs = bsum[blockIdx.x];
        int4 o = *(int4*)(off + base);
        o.x += bs; o.y += bs; o.z += bs; o.w += bs;
        *(int4*)(off + base) = o;
        *(int4*)(cur + base) = o;
    }
}

__global__ void fill_all_kernel(const int* __restrict__ s0, const int* __restrict__ d0,
                                const int* __restrict__ s1, const int* __restrict__ d1,
                                const int* __restrict__ s2, const int* __restrict__ d2,
                                int E0, int E01, int ET,
                                int* __restrict__ cur, int* __restrict__ srt) {
    int e = blockIdx.x * blockDim.x + threadIdx.x;
    if (e >= ET) return;
    int di, sv;
    if (e < E0)       { di = d0[e];               sv = s0[e]; }
    else if (e < E01) { di = 10000 + d1[e - E0];  sv = s1[e - E0]; }
    else              { di = 60000 + d2[e - E01]; sv = s2[e - E01] + 10000; }
    int p = atomicAdd(&cur[di], 1);
    srt[p] = sv;
}

// ---------------- merged mean aggregation (split bf16 in/out, 2x unroll) ----------
__device__ __forceinline__ void acc8(float* a, uint4 v) {
    const __nv_bfloat162* p = (const __nv_bfloat162*)&v;
    #pragma unroll
    for (int i = 0; i < 4; i++) {
        float2 f = __bfloat1622float2(p[i]);
        a[2 * i] += f.x;
        a[2 * i + 1] += f.y;
    }
}
__device__ __forceinline__ void src_ptrs(int src, const __nv_bfloat16* CNh, const __nv_bfloat16* CNl,
                                         const __nv_bfloat16* CIh, const __nv_bfloat16* CIl,
                                         const __nv_bfloat16*& rh, const __nv_bfloat16*& rl) {
    if (src < 10000) { rh = CNh + (size_t)src * 768; rl = CNl + (size_t)src * 768; }
    else             { rh = CIh + (size_t)(src - 10000) * 512; rl = CIl + (size_t)(src - 10000) * 512; }
}

__global__ void agg_all_kernel(__nv_bfloat16* __restrict__ CNh, __nv_bfloat16* __restrict__ CNl,
                               __nv_bfloat16* __restrict__ CIh, __nv_bfloat16* __restrict__ CIl,
                               const int* __restrict__ off, const int* __restrict__ srt,
                               const float* __restrict__ inv) {
    const int gw   = (int)((blockIdx.x * blockDim.x + threadIdx.x) >> 5);
    const int lane = threadIdx.x & 31;
    if (gw >= NNODE) return;
    __nv_bfloat16 *oh, *ol;
    if (gw < 10000) {
        oh = CNh + (size_t)gw * 768 + 256; ol = CNl + (size_t)gw * 768 + 256;
    } else if (gw < 60000) {
        const int i = gw - 10000;
        oh = CIh + (size_t)i * 512 + 256; ol = CIl + (size_t)i * 512 + 256;
    } else {
        const int i = gw - 60000;
        oh = CNh + (size_t)i * 768 + 512; ol = CNl + (size_t)i * 768 + 512;
    }
    const int e0 = off[gw], e1 = off[gw + 1];
    const int co = lane * 8;
    float a[8];
    #pragma unroll
    for (int i = 0; i < 8; i++) a[i] = 0.f;
    int e = e0;
    for (; e + 2 <= e1; e += 2) {
        const int sA = __ldg(&srt[e]);
        const int sB = __ldg(&srt[e + 1]);
        const __nv_bfloat16 *rhA, *rlA, *rhB, *rlB;
        src_ptrs(sA, CNh, CNl, CIh, CIl, rhA, rlA);
        src_ptrs(sB, CNh, CNl, CIh, CIl, rhB, rlB);
        const uint4 h0 = __ldg((const uint4*)(rhA + co));
        const uint4 l0 = __ldg((const uint4*)(rlA + co));
        const uint4 h1 = __ldg((const uint4*)(rhB + co));
        const uint4 l1 = __ldg((const uint4*)(rlB + co));
        acc8(a, h0); acc8(a, l0);
        acc8(a, h1); acc8(a, l1);
    }
    if (e < e1) {
        const int sA = __ldg(&srt[e]);
        const __nv_bfloat16 *rhA, *rlA;
        src_ptrs(sA, CNh, CNl, CIh, CIl, rhA, rlA);
        acc8(a, __ldg((const uint4*)(rhA + co)));
        acc8(a, __ldg((const uint4*)(rlA + co)));
    }
    const float d = inv[gw];
    uint4 ho, lo_;
    uint32_t* hp = (uint32_t*)&ho;
    uint32_t* lp = (uint32_t*)&lo_;
    #pragma unroll
    for (int i = 0; i < 4; i++) {
        float v0 = a[2 * i] * d, v1 = a[2 * i + 1] * d;
        __nv_bfloat16 h0, l0, h1, l1;
        split_bf(v0, h0, l0);
        split_bf(v1, h1, l1);
        hp[i] = pack_bf2(h0, h1);
        lp[i] = pack_bf2(l0, l1);
    }
    *(uint4*)(oh + co) = ho;
    *(uint4*)(ol + co) = lo_;
}

// ---------------- final projection ----------------
__global__ __launch_bounds__(256) void out_proj_kernel(
    const __nv_bfloat16* __restrict__ Xh, const __nv_bfloat16* __restrict__ Xl,
    const float* __restrict__ W, const float* __restrict__ b,
    float* __restrict__ out) {
    __shared__ float sW[H * OUTD];
    for (int i = threadIdx.x; i < H * OUTD; i += 256) sW[i] = W[i];
    __syncthreads();
    const int i = blockIdx.x * 32 + ((int)threadIdx.x >> 3);
    const int o = threadIdx.x & 7;
    if (i >= N_NEWS) return;
    float s = b[o];
    const __nv_bfloat16* xh = Xh + (size_t)i * 768;
    const __nv_bfloat16* xl = Xl + (size_t)i * 768;
    #pragma unroll 8
    for (int j = 0; j < H; j++) {
        float x = __bfloat162float(xh[j]) + __bfloat162float(xl[j]);
        s += x * sW[j * OUTD + o];
    }
    out[i * OUTD + o] = s;
}

// ---------------- launch ----------------
extern "C" void kernel_launch(void* const* d_in, const int* in_sizes, int n_in,
                              void* d_out, int out_size) {
    const float* x_news = (const float*)d_in[0];
    const float* x_int  = (const float*)d_in[1];
    const float* Wn     = (const float*)d_in[2];
    const float* bn     = (const float*)d_in[3];
    const float* Wi     = (const float*)d_in[4];
    const float* bi     = (const float*)d_in[5];
    const float* W_rel  = (const float*)d_in[6];
    const float* W_root = (const float*)d_in[7];
    const float* conv_b = (const float*)d_in[8];
    const float* out_W  = (const float*)d_in[9];
    const float* out_b  = (const float*)d_in[10];
    const int* e0s = (const int*)d_in[11];
    const int* e0d = (const int*)d_in[12];
    const int* e1s = (const int*)d_in[13];
    const int* e1d = (const int*)d_in[14];
    const int* e2s = (const int*)d_in[15];
    const int* e2d = (const int*)d_in[16];
    const int E0 = in_sizes[11], E1 = in_sizes[13], E2 = in_sizes[15];
    const int E01 = E0 + E1, ET = E0 + E1 + E2;
    float* out = (float*)d_out;

    __nv_bfloat16 *XSh, *XSl, *CN0h, *CN0l, *CN1h, *CN1l, *CI0h, *CI0l, *CI1h, *CI1l, *Bhi, *Blo;
    float *inv;
    int *deg, *off, *cur, *srt, *bsum;
    cudaGetSymbolAddress((void**)&XSh, g_XSh);
    cudaGetSymbolAddress((void**)&XSl, g_XSl);
    cudaGetSymbolAddress((void**)&CN0h, g_CN0h);
    cudaGetSymbolAddress((void**)&CN0l, g_CN0l);
    cudaGetSymbolAddress((void**)&CN1h, g_CN1h);
    cudaGetSymbolAddress((void**)&CN1l, g_CN1l);
    cudaGetSymbolAddress((void**)&CI0h, g_CI0h);
    cudaGetSymbolAddress((void**)&CI0l, g_CI0l);
    cudaGetSymbolAddress((void**)&CI1h, g_CI1h);
    cudaGetSymbolAddress((void**)&CI1l, g_CI1l);
    cudaGetSymbolAddress((void**)&deg, g_deg);
    cudaGetSymbolAddress((void**)&inv, g_inv);
    cudaGetSymbolAddress((void**)&off, g_off);
    cudaGetSymbolAddress((void**)&cur, g_cur);
    cudaGetSymbolAddress((void**)&srt, g_srt);
    cudaGetSymbolAddress((void**)&bsum, g_bsum);
    cudaGetSymbolAddress((void**)&Bhi, g_Bhi);
    cudaGetSymbolAddress((void**)&Blo, g_Blo);

    cudaFuncSetAttribute((const void*)mma_gemm_kernel<false>,
                         cudaFuncAttributeMaxDynamicSharedMemorySize, GSMEM);
    cudaFuncSetAttribute((const void*)mma_gemm_kernel<true>,
                         cudaFuncAttributeMaxDynamicSharedMemorySize, GSMEM);

    // launch order keeps the 4th kernel (ncu capture slot) = big encodeI GEMM
    wprep_all_kernel<<<(WTOTAL + 255) / 256, 256>>>(Wn, Wi, W_rel, W_root, Bhi, Blo);           // 0
    xsplit_kernel<<<(N_ALL * F_IN / 4 + 255) / 256, 256>>>(x_news, x_int, XSh, XSl);            // 1
    mma_gemm_kernel<false><<<dim3(2, (N_NEWS + 127) / 128), 256, GSMEM>>>(                      // 2
        XSh, XSl, Bhi + WOFF_ENCN, Blo + WOFF_ENCN, bn, CN0h, CN0l, 768, N_NEWS, F_IN);
    mma_gemm_kernel<false><<<dim3(2, (N_INT + 127) / 128), 256, GSMEM>>>(                       // 3 <- profiled
        XSh + (size_t)N_NEWS * F_IN, XSl + (size_t)N_NEWS * F_IN,
        Bhi + WOFF_ENCI, Blo + WOFF_ENCI, bi, CI0h, CI0l, 512, N_INT, F_IN);

    // CSR build
    cudaMemsetAsync(deg, 0, NNODE * sizeof(int));
    deg_all_kernel<<<(ET + 255) / 256, 256>>>(e0d, e1d, e2d, E0, E01, ET, deg);
    scan_p1<<<NB_SCAN, 256>>>(deg, off, inv, bsum);
    scan_p2<<<1, 128>>>(bsum, off, ET);
    scan_p3<<<NB_SCAN, 256>>>(off, cur, bsum);
    fill_all_kernel<<<(ET + 255) / 256, 256>>>(e0s, e0d, e1s, e1d, e2s, e2d,
                                               E0, E01, ET, cur, srt);

    __nv_bfloat16* CNhs[2] = {CN0h, CN1h};
    __nv_bfloat16* CNls[2] = {CN0l, CN1l};
    __nv_bfloat16* CIhs[2] = {CI0h, CI1h};
    __nv_bfloat16* CIls[2] = {CI0l, CI1l};
    for (int l = 0; l < 2; l++) {
        __nv_bfloat16 *CNch = CNhs[l & 1], *CNcl = CNls[l & 1];
        __nv_bfloat16 *CIch = CIhs[l & 1], *CIcl = CIls[l & 1];
        __nv_bfloat16 *CNnh = CNhs[(l + 1) & 1], *CNnl = CNls[(l + 1) & 1];
        __nv_bfloat16 *CInh = CIhs[(l + 1) & 1], *CInl = CIls[(l + 1) & 1];

        agg_all_kernel<<<(NNODE * 32 + 255) / 256, 256>>>(CNch, CNcl, CIch, CIcl, off, srt, inv);

        mma_gemm_kernel<true><<<dim3(2, (N_NEWS + 127) / 128), 256, GSMEM>>>(
            CNch, CNcl, Bhi + WOFF_LN(l), Blo + WOFF_LN(l), conv_b + (size_t)l * H,
            CNnh, CNnl, 768, N_NEWS, 768);
        mma_gemm_kernel<true><<<dim3(2, (N_INT + 127) / 128), 256, GSMEM>>>(
            CIch, CIcl, Bhi + WOFF_LI(l), Blo + WOFF_LI(l), conv_b + (size_t)l * H,
            CInh, CInl, 512, N_INT, 512);
    }

    out_proj_kernel<<<(N_NEWS + 31) / 32, 256>>>(CN0h, CN0l, out_W, out_b, out);
}

// round 14
// speedup vs baseline: 1.7028x; 1.1354x over previous
#include <cuda_runtime.h>
#include <cuda_bf16.h>
#include <cstdint>
#include <cstddef>

// Problem constants
#define N_NEWS 10000
#define N_INT  50000
#define N_ALL  60000
#define F_IN   768
#define H      256
#define OUTD   8
#define NNODE  70000          // [0,10000) r0-news, [10000,60000) r1-int, [60000,70000) r2-news
#define ETOT   1300000
#define NB_SCAN 69
#define YN_NEWS 79            // ceil(10000/128)
#define YN_INT  391           // ceil(50000/128)

// ---------------- device scratch ----------------
__device__ __nv_bfloat16 g_XSh[N_ALL * F_IN], g_XSl[N_ALL * F_IN];

// Activations as SPLIT bf16 (hi/lo), concatenated-K layout:
//   CN*[10000][768]: cols 0-255 X_news, 256-511 A0, 512-767 A2
//   CI*[50000][512]: cols 0-255 X_int,  256-511 A1
__device__ __nv_bfloat16 g_CN0h[N_NEWS * 768], g_CN0l[N_NEWS * 768];
__device__ __nv_bfloat16 g_CN1h[N_NEWS * 768], g_CN1l[N_NEWS * 768];
__device__ __nv_bfloat16 g_CI0h[N_INT * 512],  g_CI0l[N_INT * 512];
__device__ __nv_bfloat16 g_CI1h[N_INT * 512],  g_CI1l[N_INT * 512];

__device__ int   g_deg[NNODE];
__device__ float g_inv[NNODE];
__device__ int   g_off[NNODE + 1];
__device__ int   g_cur[NNODE];
__device__ int   g_srt[ETOT];
__device__ int   g_bsum[NB_SCAN];

// Split/transposed weights, [256 N][K] bf16, hi & lo, concatenated layout.
#define WOFF_ENCN 0
#define WOFF_ENCI 196608
#define WOFF_LN(l) (393216 + (l) * 327680)
#define WOFF_LI(l) (589824 + (l) * 327680)
#define WTOTAL 1048576
__device__ __nv_bfloat16 g_Bhi[WTOTAL];
__device__ __nv_bfloat16 g_Blo[WTOTAL];

// ================= helpers =================
__device__ __forceinline__ uint32_t smem_u32(const void* p) {
    uint32_t a;
    asm("{ .reg .u64 t; cvta.to.shared.u64 t, %1; cvt.u32.u64 %0, t; }" : "=r"(a) : "l"(p));
    return a;
}
__device__ __forceinline__ uint32_t pack_bf2(__nv_bfloat16 a, __nv_bfloat16 b) {
    return (uint32_t)__bfloat16_as_ushort(a) | ((uint32_t)__bfloat16_as_ushort(b) << 16);
}
__device__ __forceinline__ void ldm_x4(uint32_t& r0, uint32_t& r1, uint32_t& r2, uint32_t& r3,
                                       uint32_t addr) {
    asm volatile("ldmatrix.sync.aligned.m8n8.x4.shared.b16 {%0,%1,%2,%3}, [%4];"
                 : "=r"(r0), "=r"(r1), "=r"(r2), "=r"(r3) : "r"(addr));
}
__device__ __forceinline__ void mma_bf16(float* c, uint32_t a0, uint32_t a1, uint32_t a2,
                                         uint32_t a3, uint32_t b0, uint32_t b1) {
    asm volatile("mma.sync.aligned.m16n8k16.row.col.f32.bf16.bf16.f32 "
                 "{%0,%1,%2,%3}, {%4,%5,%6,%7}, {%8,%9}, {%0,%1,%2,%3};"
                 : "+f"(c[0]), "+f"(c[1]), "+f"(c[2]), "+f"(c[3])
                 : "r"(a0), "r"(a1), "r"(a2), "r"(a3), "r"(b0), "r"(b1));
}
__device__ __forceinline__ void cp16(uint32_t dst, const void* src) {
    asm volatile("cp.async.cg.shared.global [%0], [%1], 16;" :: "r"(dst), "l"(src));
}
__device__ __forceinline__ void cp16z(uint32_t dst, const void* src, int sz) {
    asm volatile("cp.async.cg.shared.global [%0], [%1], 16, %2;" :: "r"(dst), "l"(src), "r"(sz));
}
__device__ __forceinline__ void split_bf(float v, __nv_bfloat16& h, __nv_bfloat16& l) {
    h = __float2bfloat16(v);
    l = __float2bfloat16(v - __bfloat162float(h));
}

// ================= pipelined HMMA GEMM (3-term bf16 split) =================
// Two independent GEMM segments in ONE launch: blockIdx.y < yN -> segment 0
// (news), else segment 1 (interaction). Packs the small GEMM's CTAs into the
// big GEMM's partial waves without needing multi-stream capture.
// Per segment: C[M,0:256 of ldc] = A[M][K] @ B[K,256], A/B split bf16 hi/lo.
// Block 128x128 (grid.x=2 covers N=256), BK=32, 8 warps (4m x 2n).
#define BUFSZ 40960
#define GSMEM (2 * BUFSZ)

struct GemmSeg {
    const __nv_bfloat16 *Ah, *Al, *Bh, *Bl;
    const float* bias;
    __nv_bfloat16 *Ch, *Cl;
    int ldc, M, K;
};

__device__ __forceinline__ void gemm_ldA(uint32_t bufb,
                                         const __nv_bfloat16* __restrict__ Ahi,
                                         const __nv_bfloat16* __restrict__ Alo,
                                         int K, int M, int row0, int fRow, int fHalf, int k0) {
    const int r = row0 + fRow;
    const int sz = (r < M) ? 16 : 0;
    const int rc = (r < M) ? r : (M - 1);
    const size_t gb = (size_t)rc * K + k0 + fHalf * 16;
    const uint32_t d = bufb + (uint32_t)(fRow * 80 + fHalf * 32);
    cp16z(d,              Ahi + gb,     sz);
    cp16z(d + 16,         Ahi + gb + 8, sz);
    cp16z(d + 10240,      Alo + gb,     sz);
    cp16z(d + 10240 + 16, Alo + gb + 8, sz);
}
__device__ __forceinline__ void gemm_ldB(uint32_t bufb, const __nv_bfloat16* __restrict__ Bth,
                                         const __nv_bfloat16* __restrict__ Btl,
                                         int K, int col0, int fRow, int fHalf, int k0) {
    const size_t gb = (size_t)(col0 + fRow) * K + k0 + fHalf * 16;
    const uint32_t d = bufb + 20480 + (uint32_t)(fRow * 80 + fHalf * 32);
    cp16(d,              Bth + gb);
    cp16(d + 16,         Bth + gb + 8);
    cp16(d + 10240,      Btl + gb);
    cp16(d + 10240 + 16, Btl + gb + 8);
}

template <bool RELU>
__global__ __launch_bounds__(256, 2) void mma_gemm2_kernel(GemmSeg s0, GemmSeg s1, int yN) {
    extern __shared__ char smem[];
    const uint32_t sb = smem_u32(smem);
    const int tid  = threadIdx.x;
    const int wid  = tid >> 5;
    const int lane = tid & 31;
    const int wm   = wid & 3;
    const int wn   = wid >> 2;
    const bool isSeg1 = ((int)blockIdx.y >= yN);
    const GemmSeg s = isSeg1 ? s1 : s0;
    const int row0 = (isSeg1 ? ((int)blockIdx.y - yN) : (int)blockIdx.y) * 128;
    const int col0 = blockIdx.x * 128;
    const int fRow = tid >> 1;
    const int fHalf = tid & 1;
    const int M = s.M, K = s.K, ldc = s.ldc;

    float acc[2][8][4];
    #pragma unroll
    for (int i = 0; i < 2; i++)
        #pragma unroll
        for (int j = 0; j < 8; j++)
            #pragma unroll
            for (int q = 0; q < 4; q++) acc[i][j][q] = 0.f;

    const int nchunks = K >> 5;

    const uint32_t aRowOff =
        (uint32_t)(wm * 32 + ((lane >> 3) & 1) * 8 + (lane & 7)) * 80 + (lane >> 4) * 16;
    const uint32_t bRowBase =
        (uint32_t)(wn * 64 + ((lane >> 4) & 1) * 8 + (lane & 7)) * 80 + ((lane >> 3) & 1) * 16;

    gemm_ldA(sb, s.Ah, s.Al, K, M, row0, fRow, fHalf, 0);
    gemm_ldB(sb, s.Bh, s.Bl, K, col0, fRow, fHalf, 0);
    asm volatile("cp.async.commit_group;" ::: "memory");
    asm volatile("cp.async.wait_group 0;" ::: "memory");
    __syncthreads();

    for (int c = 0; c < nchunks; c++) {
        const int b = c & 1;
        const bool nxt = (c + 1) < nchunks;
        if (nxt) {
            const int k0 = (c + 1) << 5;
            gemm_ldA(sb + (b ^ 1) * BUFSZ, s.Ah, s.Al, K, M, row0, fRow, fHalf, k0);
            gemm_ldB(sb + (b ^ 1) * BUFSZ, s.Bh, s.Bl, K, col0, fRow, fHalf, k0);
            asm volatile("cp.async.commit_group;" ::: "memory");
        }

        const uint32_t aHb = sb + b * BUFSZ;
        const uint32_t aLb = aHb + 10240;
        const uint32_t bHb = aHb + 20480;
        const uint32_t bLb = aHb + 30720;
        #pragma unroll
        for (int kk = 0; kk < 2; kk++) {
            const uint32_t kOff = kk * 32;
            uint32_t ah[2][4], al[2][4];
            #pragma unroll
            for (int mt = 0; mt < 2; mt++) {
                const uint32_t roff = aRowOff + (uint32_t)(mt * 16) * 80 + kOff;
                ldm_x4(ah[mt][0], ah[mt][1], ah[mt][2], ah[mt][3], aHb + roff);
                ldm_x4(al[mt][0], al[mt][1], al[mt][2], al[mt][3], aLb + roff);
            }
            #pragma unroll
            for (int ng = 0; ng < 4; ng++) {
                const uint32_t boff = bRowBase + (uint32_t)(ng * 16) * 80 + kOff;
                uint32_t bh[4], bl[4];
                ldm_x4(bh[0], bh[1], bh[2], bh[3], bHb + boff);
                ldm_x4(bl[0], bl[1], bl[2], bl[3], bLb + boff);
                #pragma unroll
                for (int mt = 0; mt < 2; mt++)
                    #pragma unroll
                    for (int h = 0; h < 2; h++)
                        mma_bf16(acc[mt][ng * 2 + h], ah[mt][0], ah[mt][1], ah[mt][2], ah[mt][3],
                                 bh[2 * h], bh[2 * h + 1]);
                #pragma unroll
                for (int mt = 0; mt < 2; mt++)
                    #pragma unroll
                    for (int h = 0; h < 2; h++)
                        mma_bf16(acc[mt][ng * 2 + h], ah[mt][0], ah[mt][1], ah[mt][2], ah[mt][3],
                                 bl[2 * h], bl[2 * h + 1]);
                #pragma unroll
                for (int mt = 0; mt < 2; mt++)
                    #pragma unroll
                    for (int h = 0; h < 2; h++)
                        mma_bf16(acc[mt][ng * 2 + h], al[mt][0], al[mt][1], al[mt][2], al[mt][3],
                                 bh[2 * h], bh[2 * h + 1]);
            }
        }

        if (nxt) asm volatile("cp.async.wait_group 0;" ::: "memory");
        __syncthreads();
    }

    // ---- epilogue: bias + optional relu, split to bf16 hi/lo ----
    const int colBase = col0 + wn * 64 + (lane & 3) * 2;
    #pragma unroll
    for (int mt = 0; mt < 2; mt++) {
        #pragma unroll
        for (int half = 0; half < 2; half++) {
            const int r = row0 + wm * 32 + mt * 16 + (lane >> 2) + half * 8;
            if (r < M) {
                #pragma unroll
                for (int nt = 0; nt < 8; nt++) {
                    const int c = colBase + nt * 8;
                    float v0 = acc[mt][nt][2 * half];
                    float v1 = acc[mt][nt][2 * half + 1];
                    const float2 bb = *(const float2*)(s.bias + c);
                    v0 += bb.x; v1 += bb.y;
                    if (RELU) { v0 = fmaxf(v0, 0.f); v1 = fmaxf(v1, 0.f); }
                    __nv_bfloat16 h0, l0, h1, l1;
                    split_bf(v0, h0, l0);
                    split_bf(v1, h1, l1);
                    *(uint32_t*)(s.Ch + (size_t)r * ldc + c) = pack_bf2(h0, h1);
                    *(uint32_t*)(s.Cl + (size_t)r * ldc + c) = pack_bf2(l0, l1);
                }
            }
        }
    }
}

// ---------------- x pre-split ----------------
__global__ void xsplit_kernel(const float* __restrict__ xn, const float* __restrict__ xi,
                              __nv_bfloat16* __restrict__ Xh, __nv_bfloat16* __restrict__ Xl) {
    const int base = (blockIdx.x * blockDim.x + threadIdx.x) * 4;
    if (base >= N_ALL * F_IN) return;
    const float* src = (base < N_NEWS * F_IN) ? (xn + base) : (xi + (base - N_NEWS * F_IN));
    const float4 v = *(const float4*)src;
    __nv_bfloat16 hx, lx, hy, ly, hz, lz, hw, lw;
    split_bf(v.x, hx, lx); split_bf(v.y, hy, ly);
    split_bf(v.z, hz, lz); split_bf(v.w, hw, lw);
    uint2 hp, lp;
    hp.x = pack_bf2(hx, hy); hp.y = pack_bf2(hz, hw);
    lp.x = pack_bf2(lx, ly); lp.y = pack_bf2(lz, lw);
    *(uint2*)(Xh + base) = hp;
    *(uint2*)(Xl + base) = lp;
}

// ---------------- single-launch weight prep ----------------
__global__ void wprep_all_kernel(const float* __restrict__ Wn, const float* __restrict__ Wi,
                                 const float* __restrict__ W_rel, const float* __restrict__ W_root,
                                 __nv_bfloat16* __restrict__ Bhi, __nv_bfloat16* __restrict__ Blo) {
    int idx = blockIdx.x * blockDim.x + threadIdx.x;
    if (idx >= WTOTAL) return;
    const float* src;
    int base, Kdst, koff, s;
    if (idx < 196608) {
        base = WOFF_ENCN; Kdst = 768; koff = 0; s = idx; src = Wn;
    } else if (idx < 393216) {
        base = WOFF_ENCI; Kdst = 768; koff = 0; s = idx - 196608; src = Wi;
    } else {
        int t = idx - 393216;
        const int l = (t >= 327680) ? 1 : 0;
        if (l) t -= 327680;
        if (t < 196608) {
            base = WOFF_LN(l); Kdst = 768;
            const int j = t >> 16;
            s = t & 65535;
            koff = j * 256;
            src = (j == 0) ? (W_root + l * 65536)
                           : (W_rel + (l * 3 + ((j == 1) ? 0 : 2)) * 65536);
        } else {
            t -= 196608;
            base = WOFF_LI(l); Kdst = 512;
            const int j = t >> 16;
            s = t & 65535;
            koff = j * 256;
            src = (j == 0) ? (W_root + l * 65536) : (W_rel + (l * 3 + 1) * 65536);
        }
    }
    const int k = s >> 8;
    const int n = s & 255;
    const float v = src[k * 256 + n];
    __nv_bfloat16 h, l2;
    split_bf(v, h, l2);
    const size_t d = (size_t)base + (size_t)n * Kdst + koff + k;
    Bhi[d] = h;
    Blo[d] = l2;
}

// ---------------- CSR build ----------------
__global__ void deg_all_kernel(const int* __restrict__ d0, const int* __restrict__ d1,
                               const int* __restrict__ d2, int E0, int E01, int ET,
                               int* __restrict__ deg) {
    int e = blockIdx.x * blockDim.x + threadIdx.x;
    if (e >= ET) return;
    if (e < E0)       atomicAdd(&deg[d0[e]], 1);
    else if (e < E01) atomicAdd(&deg[10000 + d1[e - E0]], 1);
    else              atomicAdd(&deg[60000 + d2[e - E01]], 1);
}

__global__ __launch_bounds__(256) void scan_p1(const int* __restrict__ deg,
                                               int* __restrict__ off,
                                               float* __restrict__ inv,
                                               int* __restrict__ bsum) {
    __shared__ int ws[8];
    const int t = (int)threadIdx.x;
    const int base = (blockIdx.x * 256 + t) * 4;
    int4 d = make_int4(0, 0, 0, 0);
    if (base < NNODE) {
        d = *(const int4*)(deg + base);
        *(float4*)(inv + base) = make_float4(
            d.x > 0 ? 1.f / (float)d.x : 0.f, d.y > 0 ? 1.f / (float)d.y : 0.f,
            d.z > 0 ? 1.f / (float)d.z : 0.f, d.w > 0 ? 1.f / (float)d.w : 0.f);
    }
    const int local = d.x + d.y + d.z + d.w;
    const int lane = t & 31, w = t >> 5;
    int v = local;
    #pragma unroll
    for (int s = 1; s < 32; s <<= 1) {
        int u = __shfl_up_sync(0xFFFFFFFFu, v, s);
        if (lane >= s) v += u;
    }
    if (lane == 31) ws[w] = v;
    __syncthreads();
    if (t == 0) {
        int run = 0;
        #pragma unroll
        for (int i = 0; i < 8; i++) { int x = ws[i]; ws[i] = run; run += x; }
        bsum[blockIdx.x] = run;
    }
    __syncthreads();
    const int excl = (v - local) + ws[w];
    if (base < NNODE) {
        off[base]     = excl;
        off[base + 1] = excl + d.x;
        off[base + 2] = excl + d.x + d.y;
        off[base + 3] = excl + d.x + d.y + d.z;
    }
}

__global__ __launch_bounds__(128) void scan_p2(int* __restrict__ bsum,
                                               int* __restrict__ off, int ET) {
    __shared__ int sh[128];
    const int t = (int)threadIdx.x;
    const int v = (t < NB_SCAN) ? bsum[t] : 0;
    sh[t] = v;
    __syncthreads();
    #pragma unroll
    for (int s = 1; s < 128; s <<= 1) {
        int u = (t >= s) ? sh[t - s] : 0;
        __syncthreads();
        sh[t] += u;
        __syncthreads();
    }
    if (t < NB_SCAN) bsum[t] = sh[t] - v;
    if (t == 0) off[NNODE] = ET;
}

__global__ __launch_bounds__(256) void scan_p3(int* __restrict__ off, int* __restrict__ cur,
                                               const int* __restrict__ bsum) {
    const int base = (blockIdx.x * 256 + (int)threadIdx.x) * 4;
    if (base < NNODE) {
        const int bs = bsum[blockIdx.x];
        int4 o = *(int4*)(off + base);
        o.x += bs; o.y += bs; o.z += bs; o.w += bs;
        *(int4*)(off + base) = o;
        *(int4*)(cur + base) = o;
    }
}

__global__ void fill_all_kernel(const int* __restrict__ s0, const int* __restrict__ d0,
                                const int* __restrict__ s1, const int* __restrict__ d1,
                                const int* __restrict__ s2, const int* __restrict__ d2,
                                int E0, int E01, int ET,
                                int* __restrict__ cur, int* __restrict__ srt) {
    int e = blockIdx.x * blockDim.x + threadIdx.x;
    if (e >= ET) return;
    int di, sv;
    if (e < E0)       { di = d0[e];               sv = s0[e]; }
    else if (e < E01) { di = 10000 + d1[e - E0];  sv = s1[e - E0]; }
    else              { di = 60000 + d2[e - E01]; sv = s2[e - E01] + 10000; }
    int p = atomicAdd(&cur[di], 1);
    srt[p] = sv;
}

// ---------------- merged mean aggregation (split bf16 in/out, 2x unroll) ----------
__device__ __forceinline__ void acc8(float* a, uint4 v) {
    const __nv_bfloat162* p = (const __nv_bfloat162*)&v;
    #pragma unroll
    for (int i = 0; i < 4; i++) {
        float2 f = __bfloat1622float2(p[i]);
        a[2 * i] += f.x;
        a[2 * i + 1] += f.y;
    }
}
__device__ __forceinline__ void src_ptrs(int src, const __nv_bfloat16* CNh, const __nv_bfloat16* CNl,
                                         const __nv_bfloat16* CIh, const __nv_bfloat16* CIl,
                                         const __nv_bfloat16*& rh, const __nv_bfloat16*& rl) {
    if (src < 10000) { rh = CNh + (size_t)src * 768; rl = CNl + (size_t)src * 768; }
    else             { rh = CIh + (size_t)(src - 10000) * 512; rl = CIl + (size_t)(src - 10000) * 512; }
}

__global__ void agg_all_kernel(__nv_bfloat16* __restrict__ CNh, __nv_bfloat16* __restrict__ CNl,
                               __nv_bfloat16* __restrict__ CIh, __nv_bfloat16* __restrict__ CIl,
                               const int* __restrict__ off, const int* __restrict__ srt,
                               const float* __restrict__ inv) {
    const int gw   = (int)((blockIdx.x * blockDim.x + threadIdx.x) >> 5);
    const int lane = threadIdx.x & 31;
    if (gw >= NNODE) return;
    __nv_bfloat16 *oh, *ol;
    if (gw < 10000) {
        oh = CNh + (size_t)gw * 768 + 256; ol = CNl + (size_t)gw * 768 + 256;
    } else if (gw < 60000) {
        const int i = gw - 10000;
        oh = CIh + (size_t)i * 512 + 256; ol = CIl + (size_t)i * 512 + 256;
    } else {
        const int i = gw - 60000;
        oh = CNh + (size_t)i * 768 + 512; ol = CNl + (size_t)i * 768 + 512;
    }
    const int e0 = off[gw], e1 = off[gw + 1];
    const int co = lane * 8;
    float a[8];
    #pragma unroll
    for (int i = 0; i < 8; i++) a[i] = 0.f;
    int e = e0;
    for (; e + 2 <= e1; e += 2) {
        const int sA = __ldg(&srt[e]);
        const int sB = __ldg(&srt[e + 1]);
        const __nv_bfloat16 *rhA, *rlA, *rhB, *rlB;
        src_ptrs(sA, CNh, CNl, CIh, CIl, rhA, rlA);
        src_ptrs(sB, CNh, CNl, CIh, CIl, rhB, rlB);
        const uint4 h0 = __ldg((const uint4*)(rhA + co));
        const uint4 l0 = __ldg((const uint4*)(rlA + co));
        const uint4 h1 = __ldg((const uint4*)(rhB + co));
        const uint4 l1 = __ldg((const uint4*)(rlB + co));
        acc8(a, h0); acc8(a, l0);
        acc8(a, h1); acc8(a, l1);
    }
    if (e < e1) {
        const int sA = __ldg(&srt[e]);
        const __nv_bfloat16 *rhA, *rlA;
        src_ptrs(sA, CNh, CNl, CIh, CIl, rhA, rlA);
        acc8(a, __ldg((const uint4*)(rhA + co)));
        acc8(a, __ldg((const uint4*)(rlA + co)));
    }
    const float d = inv[gw];
    uint4 ho, lo_;
    uint32_t* hp = (uint32_t*)&ho;
    uint32_t* lp = (uint32_t*)&lo_;
    #pragma unroll
    for (int i = 0; i < 4; i++) {
        float v0 = a[2 * i] * d, v1 = a[2 * i + 1] * d;
        __nv_bfloat16 h0, l0, h1, l1;
        split_bf(v0, h0, l0);
        split_bf(v1, h1, l1);
        hp[i] = pack_bf2(h0, h1);
        lp[i] = pack_bf2(l0, l1);
    }
    *(uint4*)(oh + co) = ho;
    *(uint4*)(ol + co) = lo_;
}

// ---------------- final projection ----------------
__global__ __launch_bounds__(256) void out_proj_kernel(
    const __nv_bfloat16* __restrict__ Xh, const __nv_bfloat16* __restrict__ Xl,
    const float* __restrict__ W, const float* __restrict__ b,
    float* __restrict__ out) {
    __shared__ float sW[H * OUTD];
    for (int i = threadIdx.x; i < H * OUTD; i += 256) sW[i] = W[i];
    __syncthreads();
    const int i = blockIdx.x * 32 + ((int)threadIdx.x >> 3);
    const int o = threadIdx.x & 7;
    if (i >= N_NEWS) return;
    float s = b[o];
    const __nv_bfloat16* xh = Xh + (size_t)i * 768;
    const __nv_bfloat16* xl = Xl + (size_t)i * 768;
    #pragma unroll 8
    for (int j = 0; j < H; j++) {
        float x = __bfloat162float(xh[j]) + __bfloat162float(xl[j]);
        s += x * sW[j * OUTD + o];
    }
    out[i * OUTD + o] = s;
}

// ---------------- launch ----------------
extern "C" void kernel_launch(void* const* d_in, const int* in_sizes, int n_in,
                              void* d_out, int out_size) {
    const float* x_news = (const float*)d_in[0];
    const float* x_int  = (const float*)d_in[1];
    const float* Wn     = (const float*)d_in[2];
    const float* bn     = (const float*)d_in[3];
    const float* Wi     = (const float*)d_in[4];
    const float* bi     = (const float*)d_in[5];
    const float* W_rel  = (const float*)d_in[6];
    const float* W_root = (const float*)d_in[7];
    const float* conv_b = (const float*)d_in[8];
    const float* out_W  = (const float*)d_in[9];
    const float* out_b  = (const float*)d_in[10];
    const int* e0s = (const int*)d_in[11];
    const int* e0d = (const int*)d_in[12];
    const int* e1s = (const int*)d_in[13];
    const int* e1d = (const int*)d_in[14];
    const int* e2s = (const int*)d_in[15];
    const int* e2d = (const int*)d_in[16];
    const int E0 = in_sizes[11], E1 = in_sizes[13], E2 = in_sizes[15];
    const int E01 = E0 + E1, ET = E0 + E1 + E2;
    float* out = (float*)d_out;

    __nv_bfloat16 *XSh, *XSl, *CN0h, *CN0l, *CN1h, *CN1l, *CI0h, *CI0l, *CI1h, *CI1l, *Bhi, *Blo;
    float *inv;
    int *deg, *off, *cur, *srt, *bsum;
    cudaGetSymbolAddress((void**)&XSh, g_XSh);
    cudaGetSymbolAddress((void**)&XSl, g_XSl);
    cudaGetSymbolAddress((void**)&CN0h, g_CN0h);
    cudaGetSymbolAddress((void**)&CN0l, g_CN0l);
    cudaGetSymbolAddress((void**)&CN1h, g_CN1h);
    cudaGetSymbolAddress((void**)&CN1l, g_CN1l);
    cudaGetSymbolAddress((void**)&CI0h, g_CI0h);
    cudaGetSymbolAddress((void**)&CI0l, g_CI0l);
    cudaGetSymbolAddress((void**)&CI1h, g_CI1h);
    cudaGetSymbolAddress((void**)&CI1l, g_CI1l);
    cudaGetSymbolAddress((void**)&deg, g_deg);
    cudaGetSymbolAddress((void**)&inv, g_inv);
    cudaGetSymbolAddress((void**)&off, g_off);
    cudaGetSymbolAddress((void**)&cur, g_cur);
    cudaGetSymbolAddress((void**)&srt, g_srt);
    cudaGetSymbolAddress((void**)&bsum, g_bsum);
    cudaGetSymbolAddress((void**)&Bhi, g_Bhi);
    cudaGetSymbolAddress((void**)&Blo, g_Blo);

    cudaFuncSetAttribute((const void*)mma_gemm2_kernel<false>,
                         cudaFuncAttributeMaxDynamicSharedMemorySize, GSMEM);
    cudaFuncSetAttribute((const void*)mma_gemm2_kernel<true>,
                         cudaFuncAttributeMaxDynamicSharedMemorySize, GSMEM);

    // order: wprep(1), xsplit(2), deg(3), merged-encode(4 <- ncu capture slot)
    wprep_all_kernel<<<(WTOTAL + 255) / 256, 256>>>(Wn, Wi, W_rel, W_root, Bhi, Blo);
    xsplit_kernel<<<(N_ALL * F_IN / 4 + 255) / 256, 256>>>(x_news, x_int, XSh, XSl);
    cudaMemsetAsync(deg, 0, NNODE * sizeof(int));
    deg_all_kernel<<<(ET + 255) / 256, 256>>>(e0d, e1d, e2d, E0, E01, ET, deg);

    // merged encode: news + interaction in one launch
    {
        GemmSeg sn = {XSh, XSl, Bhi + WOFF_ENCN, Blo + WOFF_ENCN, bn,
                      CN0h, CN0l, 768, N_NEWS, F_IN};
        GemmSeg si = {XSh + (size_t)N_NEWS * F_IN, XSl + (size_t)N_NEWS * F_IN,
                      Bhi + WOFF_ENCI, Blo + WOFF_ENCI, bi,
                      CI0h, CI0l, 512, N_INT, F_IN};
        mma_gemm2_kernel<false><<<dim3(2, YN_NEWS + YN_INT), 256, GSMEM>>>(sn, si, YN_NEWS);
    }

    // rest of CSR build
    scan_p1<<<NB_SCAN, 256>>>(deg, off, inv, bsum);
    scan_p2<<<1, 128>>>(bsum, off, ET);
    scan_p3<<<NB_SCAN, 256>>>(off, cur, bsum);
    fill_all_kernel<<<(ET + 255) / 256, 256>>>(e0s, e0d, e1s, e1d, e2s, e2d,
                                               E0, E01, ET, cur, srt);

    __nv_bfloat16* CNhs[2] = {CN0h, CN1h};
    __nv_bfloat16* CNls[2] = {CN0l, CN1l};
    __nv_bfloat16* CIhs[2] = {CI0h, CI1h};
    __nv_bfloat16* CIls[2] = {CI0l, CI1l};
    for (int l = 0; l < 2; l++) {
        __nv_bfloat16 *CNch = CNhs[l & 1], *CNcl = CNls[l & 1];
        __nv_bfloat16 *CIch = CIhs[l & 1], *CIcl = CIls[l & 1];
        __nv_bfloat16 *CNnh = CNhs[(l + 1) & 1], *CNnl = CNls[(l + 1) & 1];
        __nv_bfloat16 *CInh = CIhs[(l + 1) & 1], *CInl = CIls[(l + 1) & 1];

        agg_all_kernel<<<(NNODE * 32 + 255) / 256, 256>>>(CNch, CNcl, CIch, CIcl, off, srt, inv);

        // merged layer GEMM: news + interaction in one launch
        GemmSeg sn = {CNch, CNcl, Bhi + WOFF_LN(l), Blo + WOFF_LN(l), conv_b + (size_t)l * H,
                      CNnh, CNnl, 768, N_NEWS, 768};
        GemmSeg si = {CIch, CIcl, Bhi + WOFF_LI(l), Blo + WOFF_LI(l), conv_b + (size_t)l * H,
                      CInh, CInl, 512, N_INT, 512};
        mma_gemm2_kernel<true><<<dim3(2, YN_NEWS + YN_INT), 256, GSMEM>>>(sn, si, YN_NEWS);
    }

    out_proj_kernel<<<(N_NEWS + 31) / 32, 256>>>(CN0h, CN0l, out_W, out_b, out);
}

// round 15
// speedup vs baseline: 1.7360x; 1.0195x over previous
#include <cuda_runtime.h>
#include <cuda_bf16.h>
#include <cstdint>
#include <cstddef>

// Problem constants
#define N_NEWS 10000
#define N_INT  50000
#define N_ALL  60000
#define F_IN   768
#define H      256
#define OUTD   8
#define NNODE  70000          // [0,10000) r0-news, [10000,60000) r1-int, [60000,70000) r2-news
#define ETOT   1300000
#define NB_SCAN 69
#define YN_NEWS 157           // ceil(10000/64)
#define YN_INT  782           // ceil(50000/64)

// ---------------- device scratch ----------------
__device__ __nv_bfloat16 g_XSh[N_ALL * F_IN], g_XSl[N_ALL * F_IN];

// Activations as SPLIT bf16 (hi/lo), concatenated-K layout:
//   CN*[10000][768]: cols 0-255 X_news, 256-511 A0, 512-767 A2
//   CI*[50000][512]: cols 0-255 X_int,  256-511 A1
__device__ __nv_bfloat16 g_CN0h[N_NEWS * 768], g_CN0l[N_NEWS * 768];
__device__ __nv_bfloat16 g_CN1h[N_NEWS * 768], g_CN1l[N_NEWS * 768];
__device__ __nv_bfloat16 g_CI0h[N_INT * 512],  g_CI0l[N_INT * 512];
__device__ __nv_bfloat16 g_CI1h[N_INT * 512],  g_CI1l[N_INT * 512];

__device__ int   g_deg[NNODE];
__device__ float g_inv[NNODE];
__device__ int   g_off[NNODE + 1];
__device__ int   g_cur[NNODE];
__device__ int   g_srt[ETOT];
__device__ int   g_bsum[NB_SCAN];

// Split/transposed weights, [256 N][K] bf16, hi & lo, concatenated layout.
#define WOFF_ENCN 0
#define WOFF_ENCI 196608
#define WOFF_LN(l) (393216 + (l) * 327680)
#define WOFF_LI(l) (589824 + (l) * 327680)
#define WTOTAL 1048576
__device__ __nv_bfloat16 g_Bhi[WTOTAL];
__device__ __nv_bfloat16 g_Blo[WTOTAL];

// ================= helpers =================
__device__ __forceinline__ uint32_t smem_u32(const void* p) {
    uint32_t a;
    asm("{ .reg .u64 t; cvta.to.shared.u64 t, %1; cvt.u32.u64 %0, t; }" : "=r"(a) : "l"(p));
    return a;
}
__device__ __forceinline__ uint32_t pack_bf2(__nv_bfloat16 a, __nv_bfloat16 b) {
    return (uint32_t)__bfloat16_as_ushort(a) | ((uint32_t)__bfloat16_as_ushort(b) << 16);
}
__device__ __forceinline__ void ldm_x4(uint32_t& r0, uint32_t& r1, uint32_t& r2, uint32_t& r3,
                                       uint32_t addr) {
    asm volatile("ldmatrix.sync.aligned.m8n8.x4.shared.b16 {%0,%1,%2,%3}, [%4];"
                 : "=r"(r0), "=r"(r1), "=r"(r2), "=r"(r3) : "r"(addr));
}
__device__ __forceinline__ void mma_bf16(float* c, uint32_t a0, uint32_t a1, uint32_t a2,
                                         uint32_t a3, uint32_t b0, uint32_t b1) {
    asm volatile("mma.sync.aligned.m16n8k16.row.col.f32.bf16.bf16.f32 "
                 "{%0,%1,%2,%3}, {%4,%5,%6,%7}, {%8,%9}, {%0,%1,%2,%3};"
                 : "+f"(c[0]), "+f"(c[1]), "+f"(c[2]), "+f"(c[3])
                 : "r"(a0), "r"(a1), "r"(a2), "r"(a3), "r"(b0), "r"(b1));
}
__device__ __forceinline__ void cp16(uint32_t dst, const void* src) {
    asm volatile("cp.async.cg.shared.global [%0], [%1], 16;" :: "r"(dst), "l"(src));
}
__device__ __forceinline__ void cp16z(uint32_t dst, const void* src, int sz) {
    asm volatile("cp.async.cg.shared.global [%0], [%1], 16, %2;" :: "r"(dst), "l"(src), "r"(sz));
}
__device__ __forceinline__ void split_bf(float v, __nv_bfloat16& h, __nv_bfloat16& l) {
    h = __float2bfloat16(v);
    l = __float2bfloat16(v - __bfloat162float(h));
}

// ================= pipelined HMMA GEMM (3-term bf16 split) =================
// Two independent GEMM segments in ONE launch (blockIdx.y < yN -> seg 0).
// Per segment: C[M,0:256 of ldc] = A[M][K] @ B[K,256], A/B split bf16 hi/lo.
// Block tile 64(M) x 128(N), grid.x=2 covers N=256. 8 warps = 2m x 4n,
// warp tile 32x32 -> acc 32 regs/thread -> 3 CTAs/SM (24 warps/SM).
// Dyn SMEM per buf: Ah@0(5120), Al@5120, Bh@10240(10240), Bl@20480 -> 30720 B.
#define BUFSZ 30720
#define GSMEM (2 * BUFSZ)

struct GemmSeg {
    const __nv_bfloat16 *Ah, *Al, *Bh, *Bl;
    const float* bias;
    __nv_bfloat16 *Ch, *Cl;
    int ldc, M, K;
};

// A tile: 64 rows x 32 bf16 (hi+lo). Threads 0..127: fRow=tid>>1, fHalf=tid&1.
__device__ __forceinline__ void gemm_ldA(uint32_t bufb,
                                         const __nv_bfloat16* __restrict__ Ahi,
                                         const __nv_bfloat16* __restrict__ Alo,
                                         int K, int M, int row0, int tid, int k0) {
    if (tid >= 128) return;
    const int fRow = tid >> 1;
    const int fHalf = tid & 1;
    const int r = row0 + fRow;
    const int sz = (r < M) ? 16 : 0;
    const int rc = (r < M) ? r : (M - 1);
    const size_t gb = (size_t)rc * K + k0 + fHalf * 16;
    const uint32_t d = bufb + (uint32_t)(fRow * 80 + fHalf * 32);
    cp16z(d,             Ahi + gb,     sz);
    cp16z(d + 16,        Ahi + gb + 8, sz);
    cp16z(d + 5120,      Alo + gb,     sz);
    cp16z(d + 5120 + 16, Alo + gb + 8, sz);
}
// B tile: 128 rows x 32 bf16 (hi+lo). All 256 threads: fRow=tid>>1, fHalf=tid&1.
__device__ __forceinline__ void gemm_ldB(uint32_t bufb, const __nv_bfloat16* __restrict__ Bth,
                                         const __nv_bfloat16* __restrict__ Btl,
                                         int K, int col0, int tid, int k0) {
    const int fRow = tid >> 1;
    const int fHalf = tid & 1;
    const size_t gb = (size_t)(col0 + fRow) * K + k0 + fHalf * 16;
    const uint32_t d = bufb + 10240 + (uint32_t)(fRow * 80 + fHalf * 32);
    cp16(d,              Bth + gb);
    cp16(d + 16,         Bth + gb + 8);
    cp16(d + 10240,      Btl + gb);
    cp16(d + 10240 + 16, Btl + gb + 8);
}

template <bool RELU>
__global__ __launch_bounds__(256, 3) void mma_gemm2_kernel(GemmSeg s0, GemmSeg s1, int yN) {
    extern __shared__ char smem[];
    const uint32_t sb = smem_u32(smem);
    const int tid  = threadIdx.x;
    const int wid  = tid >> 5;
    const int lane = tid & 31;
    const int wm   = wid & 1;          // 2 m-warps: rows wm*32
    const int wn   = wid >> 1;         // 4 n-warps: cols wn*32
    const bool isSeg1 = ((int)blockIdx.y >= yN);
    const GemmSeg s = isSeg1 ? s1 : s0;
    const int row0 = (isSeg1 ? ((int)blockIdx.y - yN) : (int)blockIdx.y) * 64;
    const int col0 = blockIdx.x * 128;
    const int M = s.M, K = s.K, ldc = s.ldc;

    float acc[2][4][4];                 // [mt][ng*2+h][quad] = 32 regs
    #pragma unroll
    for (int i = 0; i < 2; i++)
        #pragma unroll
        for (int j = 0; j < 4; j++)
            #pragma unroll
            for (int q = 0; q < 4; q++) acc[i][j][q] = 0.f;

    const int nchunks = K >> 5;

    const uint32_t aRowOff =
        (uint32_t)(wm * 32 + ((lane >> 3) & 1) * 8 + (lane & 7)) * 80 + (lane >> 4) * 16;
    const uint32_t bRowBase =
        (uint32_t)(wn * 32 + ((lane >> 4) & 1) * 8 + (lane & 7)) * 80 + ((lane >> 3) & 1) * 16;

    gemm_ldA(sb, s.Ah, s.Al, K, M, row0, tid, 0);
    gemm_ldB(sb, s.Bh, s.Bl, K, col0, tid, 0);
    asm volatile("cp.async.commit_group;" ::: "memory");
    asm volatile("cp.async.wait_group 0;" ::: "memory");
    __syncthreads();

    for (int c = 0; c < nchunks; c++) {
        const int b = c & 1;
        const bool nxt = (c + 1) < nchunks;
        if (nxt) {
            const int k0 = (c + 1) << 5;
            gemm_ldA(sb + (b ^ 1) * BUFSZ, s.Ah, s.Al, K, M, row0, tid, k0);
            gemm_ldB(sb + (b ^ 1) * BUFSZ, s.Bh, s.Bl, K, col0, tid, k0);
            asm volatile("cp.async.commit_group;" ::: "memory");
        }

        const uint32_t aHb = sb + b * BUFSZ;
        const uint32_t aLb = aHb + 5120;
        const uint32_t bHb = aHb + 10240;
        const uint32_t bLb = aHb + 20480;
        #pragma unroll
        for (int kk = 0; kk < 2; kk++) {
            const uint32_t kOff = kk * 32;
            uint32_t ah[2][4], al[2][4];
            #pragma unroll
            for (int mt = 0; mt < 2; mt++) {
                const uint32_t roff = aRowOff + (uint32_t)(mt * 16) * 80 + kOff;
                ldm_x4(ah[mt][0], ah[mt][1], ah[mt][2], ah[mt][3], aHb + roff);
                ldm_x4(al[mt][0], al[mt][1], al[mt][2], al[mt][3], aLb + roff);
            }
            #pragma unroll
            for (int ng = 0; ng < 2; ng++) {
                const uint32_t boff = bRowBase + (uint32_t)(ng * 16) * 80 + kOff;
                uint32_t bh[4], bl[4];
                ldm_x4(bh[0], bh[1], bh[2], bh[3], bHb + boff);
                ldm_x4(bl[0], bl[1], bl[2], bl[3], bLb + boff);
                #pragma unroll
                for (int mt = 0; mt < 2; mt++)
                    #pragma unroll
                    for (int h = 0; h < 2; h++)
                        mma_bf16(acc[mt][ng * 2 + h], ah[mt][0], ah[mt][1], ah[mt][2], ah[mt][3],
                                 bh[2 * h], bh[2 * h + 1]);
                #pragma unroll
                for (int mt = 0; mt < 2; mt++)
                    #pragma unroll
                    for (int h = 0; h < 2; h++)
                        mma_bf16(acc[mt][ng * 2 + h], ah[mt][0], ah[mt][1], ah[mt][2], ah[mt][3],
                                 bl[2 * h], bl[2 * h + 1]);
                #pragma unroll
                for (int mt = 0; mt < 2; mt++)
                    #pragma unroll
                    for (int h = 0; h < 2; h++)
                        mma_bf16(acc[mt][ng * 2 + h], al[mt][0], al[mt][1], al[mt][2], al[mt][3],
                                 bh[2 * h], bh[2 * h + 1]);
            }
        }

        if (nxt) asm volatile("cp.async.wait_group 0;" ::: "memory");
        __syncthreads();
    }

    // ---- epilogue: bias + optional relu, split to bf16 hi/lo ----
    const int colBase = col0 + wn * 32 + (lane & 3) * 2;
    #pragma unroll
    for (int mt = 0; mt < 2; mt++) {
        #pragma unroll
        for (int half = 0; half < 2; half++) {
            const int r = row0 + wm * 32 + mt * 16 + (lane >> 2) + half * 8;
            if (r < M) {
                #pragma unroll
                for (int nt = 0; nt < 4; nt++) {
                    const int c = colBase + nt * 8;
                    float v0 = acc[mt][nt][2 * half];
                    float v1 = acc[mt][nt][2 * half + 1];
                    const float2 bb = *(const float2*)(s.bias + c);
                    v0 += bb.x; v1 += bb.y;
                    if (RELU) { v0 = fmaxf(v0, 0.f); v1 = fmaxf(v1, 0.f); }
                    __nv_bfloat16 h0, l0, h1, l1;
                    split_bf(v0, h0, l0);
                    split_bf(v1, h1, l1);
                    *(uint32_t*)(s.Ch + (size_t)r * ldc + c) = pack_bf2(h0, h1);
                    *(uint32_t*)(s.Cl + (size_t)r * ldc + c) = pack_bf2(l0, l1);
                }
            }
        }
    }
}

// ---------------- x pre-split ----------------
__global__ void xsplit_kernel(const float* __restrict__ xn, const float* __restrict__ xi,
                              __nv_bfloat16* __restrict__ Xh, __nv_bfloat16* __restrict__ Xl) {
    const int base = (blockIdx.x * blockDim.x + threadIdx.x) * 4;
    if (base >= N_ALL * F_IN) return;
    const float* src = (base < N_NEWS * F_IN) ? (xn + base) : (xi + (base - N_NEWS * F_IN));
    const float4 v = *(const float4*)src;
    __nv_bfloat16 hx, lx, hy, ly, hz, lz, hw, lw;
    split_bf(v.x, hx, lx); split_bf(v.y, hy, ly);
    split_bf(v.z, hz, lz); split_bf(v.w, hw, lw);
    uint2 hp, lp;
    hp.x = pack_bf2(hx, hy); hp.y = pack_bf2(hz, hw);
    lp.x = pack_bf2(lx, ly); lp.y = pack_bf2(lz, lw);
    *(uint2*)(Xh + base) = hp;
    *(uint2*)(Xl + base) = lp;
}

// ---------------- single-launch weight prep ----------------
__global__ void wprep_all_kernel(const float* __restrict__ Wn, const float* __restrict__ Wi,
                                 const float* __restrict__ W_rel, const float* __restrict__ W_root,
                                 __nv_bfloat16* __restrict__ Bhi, __nv_bfloat16* __restrict__ Blo) {
    int idx = blockIdx.x * blockDim.x + threadIdx.x;
    if (idx >= WTOTAL) return;
    const float* src;
    int base, Kdst, koff, s;
    if (idx < 196608) {
        base = WOFF_ENCN; Kdst = 768; koff = 0; s = idx; src = Wn;
    } else if (idx < 393216) {
        base = WOFF_ENCI; Kdst = 768; koff = 0; s = idx - 196608; src = Wi;
    } else {
        int t = idx - 393216;
        const int l = (t >= 327680) ? 1 : 0;
        if (l) t -= 327680;
        if (t < 196608) {
            base = WOFF_LN(l); Kdst = 768;
            const int j = t >> 16;
            s = t & 65535;
            koff = j * 256;
            src = (j == 0) ? (W_root + l * 65536)
                           : (W_rel + (l * 3 + ((j == 1) ? 0 : 2)) * 65536);
        } else {
            t -= 196608;
            base = WOFF_LI(l); Kdst = 512;
            const int j = t >> 16;
            s = t & 65535;
            koff = j * 256;
            src = (j == 0) ? (W_root + l * 65536) : (W_rel + (l * 3 + 1) * 65536);
        }
    }
    const int k = s >> 8;
    const int n = s & 255;
    const float v = src[k * 256 + n];
    __nv_bfloat16 h, l2;
    split_bf(v, h, l2);
    const size_t d = (size_t)base + (size_t)n * Kdst + koff + k;
    Bhi[d] = h;
    Blo[d] = l2;
}

// ---------------- CSR build ----------------
__global__ void deg_all_kernel(const int* __restrict__ d0, const int* __restrict__ d1,
                               const int* __restrict__ d2, int E0, int E01, int ET,
                               int* __restrict__ deg) {
    int e = blockIdx.x * blockDim.x + threadIdx.x;
    if (e >= ET) return;
    if (e < E0)       atomicAdd(&deg[d0[e]], 1);
    else if (e < E01) atomicAdd(&deg[10000 + d1[e - E0]], 1);
    else              atomicAdd(&deg[60000 + d2[e - E01]], 1);
}

__global__ __launch_bounds__(256) void scan_p1(const int* __restrict__ deg,
                                               int* __restrict__ off,
                                               float* __restrict__ inv,
                                               int* __restrict__ bsum) {
    __shared__ int ws[8];
    const int t = (int)threadIdx.x;
    const int base = (blockIdx.x * 256 + t) * 4;
    int4 d = make_int4(0, 0, 0, 0);
    if (base < NNODE) {
        d = *(const int4*)(deg + base);
        *(float4*)(inv + base) = make_float4(
            d.x > 0 ? 1.f / (float)d.x : 0.f, d.y > 0 ? 1.f / (float)d.y : 0.f,
            d.z > 0 ? 1.f / (float)d.z : 0.f, d.w > 0 ? 1.f / (float)d.w : 0.f);
    }
    const int local = d.x + d.y + d.z + d.w;
    const int lane = t & 31, w = t >> 5;
    int v = local;
    #pragma unroll
    for (int s = 1; s < 32; s <<= 1) {
        int u = __shfl_up_sync(0xFFFFFFFFu, v, s);
        if (lane >= s) v += u;
    }
    if (lane == 31) ws[w] = v;
    __syncthreads();
    if (t == 0) {
        int run = 0;
        #pragma unroll
        for (int i = 0; i < 8; i++) { int x = ws[i]; ws[i] = run; run += x; }
        bsum[blockIdx.x] = run;
    }
    __syncthreads();
    const int excl = (v - local) + ws[w];
    if (base < NNODE) {
        off[base]     = excl;
        off[base + 1] = excl + d.x;
        off[base + 2] = excl + d.x + d.y;
        off[base + 3] = excl + d.x + d.y + d.z;
    }
}

__global__ __launch_bounds__(128) void scan_p2(int* __restrict__ bsum,
                                               int* __restrict__ off, int ET) {
    __shared__ int sh[128];
    const int t = (int)threadIdx.x;
    const int v = (t < NB_SCAN) ? bsum[t] : 0;
    sh[t] = v;
    __syncthreads();
    #pragma unroll
    for (int s = 1; s < 128; s <<= 1) {
        int u = (t >= s) ? sh[t - s] : 0;
        __syncthreads();
        sh[t] += u;
        __syncthreads();
    }
    if (t < NB_SCAN) bsum[t] = sh[t] - v;
    if (t == 0) off[NNODE] = ET;
}

__global__ __launch_bounds__(256) void scan_p3(int* __restrict__ off, int* __restrict__ cur,
                                               const int* __restrict__ bsum) {
    const int base = (blockIdx.x * 256 + (int)threadIdx.x) * 4;
    if (base < NNODE) {
        const int bs = bsum[blockIdx.x];
        int4 o = *(int4*)(off + base);
        o.x += bs; o.y += bs; o.z += bs; o.w += bs;
        *(int4*)(off + base) = o;
        *(int4*)(cur + base) = o;
    }
}

__global__ void fill_all_kernel(const int* __restrict__ s0, const int* __restrict__ d0,
                                const int* __restrict__ s1, const int* __restrict__ d1,
                                const int* __restrict__ s2, const int* __restrict__ d2,
                                int E0, int E01, int ET,
                                int* __restrict__ cur, int* __restrict__ srt) {
    int e = blockIdx.x * blockDim.x + threadIdx.x;
    if (e >= ET) return;
    int di, sv;
    if (e < E0)       { di = d0[e];               sv = s0[e]; }
    else if (e < E01) { di = 10000 + d1[e - E0];  sv = s1[e - E0]; }
    else              { di = 60000 + d2[e - E01]; sv = s2[e - E01] + 10000; }
    int p = atomicAdd(&cur[di], 1);
    srt[p] = sv;
}

// ---------------- merged mean aggregation (split bf16 in/out, 2x unroll) ----------
__device__ __forceinline__ void acc8(float* a, uint4 v) {
    const __nv_bfloat162* p = (const __nv_bfloat162*)&v;
    #pragma unroll
    for (int i = 0; i < 4; i++) {
        float2 f = __bfloat1622float2(p[i]);
        a[2 * i] += f.x;
        a[2 * i + 1] += f.y;
    }
}
__device__ __forceinline__ void src_ptrs(int src, const __nv_bfloat16* CNh, const __nv_bfloat16* CNl,
                                         const __nv_bfloat16* CIh, const __nv_bfloat16* CIl,
                                         const __nv_bfloat16*& rh, const __nv_bfloat16*& rl) {
    if (src < 10000) { rh = CNh + (size_t)src * 768; rl = CNl + (size_t)src * 768; }
    else             { rh = CIh + (size_t)(src - 10000) * 512; rl = CIl + (size_t)(src - 10000) * 512; }
}

__global__ void agg_all_kernel(__nv_bfloat16* __restrict__ CNh, __nv_bfloat16* __restrict__ CNl,
                               __nv_bfloat16* __restrict__ CIh, __nv_bfloat16* __restrict__ CIl,
                               const int* __restrict__ off, const int* __restrict__ srt,
                               const float* __restrict__ inv) {
    const int gw   = (int)((blockIdx.x * blockDim.x + threadIdx.x) >> 5);
    const int lane = threadIdx.x & 31;
    if (gw >= NNODE) return;
    __nv_bfloat16 *oh, *ol;
    if (gw < 10000) {
        oh = CNh + (size_t)gw * 768 + 256; ol = CNl + (size_t)gw * 768 + 256;
    } else if (gw < 60000) {
        const int i = gw - 10000;
        oh = CIh + (size_t)i * 512 + 256; ol = CIl + (size_t)i * 512 + 256;
    } else {
        const int i = gw - 60000;
        oh = CNh + (size_t)i * 768 + 512; ol = CNl + (size_t)i * 768 + 512;
    }
    const int e0 = off[gw], e1 = off[gw + 1];
    const int co = lane * 8;
    float a[8];
    #pragma unroll
    for (int i = 0; i < 8; i++) a[i] = 0.f;
    int e = e0;
    for (; e + 2 <= e1; e += 2) {
        const int sA = __ldg(&srt[e]);
        const int sB = __ldg(&srt[e + 1]);
        const __nv_bfloat16 *rhA, *rlA, *rhB, *rlB;
        src_ptrs(sA, CNh, CNl, CIh, CIl, rhA, rlA);
        src_ptrs(sB, CNh, CNl, CIh, CIl, rhB, rlB);
        const uint4 h0 = __ldg((const uint4*)(rhA + co));
        const uint4 l0 = __ldg((const uint4*)(rlA + co));
        const uint4 h1 = __ldg((const uint4*)(rhB + co));
        const uint4 l1 = __ldg((const uint4*)(rlB + co));
        acc8(a, h0); acc8(a, l0);
        acc8(a, h1); acc8(a, l1);
    }
    if (e < e1) {
        const int sA = __ldg(&srt[e]);
        const __nv_bfloat16 *rhA, *rlA;
        src_ptrs(sA, CNh, CNl, CIh, CIl, rhA, rlA);
        acc8(a, __ldg((const uint4*)(rhA + co)));
        acc8(a, __ldg((const uint4*)(rlA + co)));
    }
    const float d = inv[gw];
    uint4 ho, lo_;
    uint32_t* hp = (uint32_t*)&ho;
    uint32_t* lp = (uint32_t*)&lo_;
    #pragma unroll
    for (int i = 0; i < 4; i++) {
        float v0 = a[2 * i] * d, v1 = a[2 * i + 1] * d;
        __nv_bfloat16 h0, l0, h1, l1;
        split_bf(v0, h0, l0);
        split_bf(v1, h1, l1);
        hp[i] = pack_bf2(h0, h1);
        lp[i] = pack_bf2(l0, l1);
    }
    *(uint4*)(oh + co) = ho;
    *(uint4*)(ol + co) = lo_;
}

// ---------------- final projection ----------------
__global__ __launch_bounds__(256) void out_proj_kernel(
    const __nv_bfloat16* __restrict__ Xh, const __nv_bfloat16* __restrict__ Xl,
    const float* __restrict__ W, const float* __restrict__ b,
    float* __restrict__ out) {
    __shared__ float sW[H * OUTD];
    for (int i = threadIdx.x; i < H * OUTD; i += 256) sW[i] = W[i];
    __syncthreads();
    const int i = blockIdx.x * 32 + ((int)threadIdx.x >> 3);
    const int o = threadIdx.x & 7;
    if (i >= N_NEWS) return;
    float s = b[o];
    const __nv_bfloat16* xh = Xh + (size_t)i * 768;
    const __nv_bfloat16* xl = Xl + (size_t)i * 768;
    #pragma unroll 8
    for (int j = 0; j < H; j++) {
        float x = __bfloat162float(xh[j]) + __bfloat162float(xl[j]);
        s += x * sW[j * OUTD + o];
    }
    out[i * OUTD + o] = s;
}

// ---------------- launch ----------------
extern "C" void kernel_launch(void* const* d_in, const int* in_sizes, int n_in,
                              void* d_out, int out_size) {
    const float* x_news = (const float*)d_in[0];
    const float* x_int  = (const float*)d_in[1];
    const float* Wn     = (const float*)d_in[2];
    const float* bn     = (const float*)d_in[3];
    const float* Wi     = (const float*)d_in[4];
    const float* bi     = (const float*)d_in[5];
    const float* W_rel  = (const float*)d_in[6];
    const float* W_root = (const float*)d_in[7];
    const float* conv_b = (const float*)d_in[8];
    const float* out_W  = (const float*)d_in[9];
    const float* out_b  = (const float*)d_in[10];
    const int* e0s = (const int*)d_in[11];
    const int* e0d = (const int*)d_in[12];
    const int* e1s = (const int*)d_in[13];
    const int* e1d = (const int*)d_in[14];
    const int* e2s = (const int*)d_in[15];
    const int* e2d = (const int*)d_in[16];
    const int E0 = in_sizes[11], E1 = in_sizes[13], E2 = in_sizes[15];
    const int E01 = E0 + E1, ET = E0 + E1 + E2;
    float* out = (float*)d_out;

    __nv_bfloat16 *XSh, *XSl, *CN0h, *CN0l, *CN1h, *CN1l, *CI0h, *CI0l, *CI1h, *CI1l, *Bhi, *Blo;
    float *inv;
    int *deg, *off, *cur, *srt, *bsum;
    cudaGetSymbolAddress((void**)&XSh, g_XSh);
    cudaGetSymbolAddress((void**)&XSl, g_XSl);
    cudaGetSymbolAddress((void**)&CN0h, g_CN0h);
    cudaGetSymbolAddress((void**)&CN0l, g_CN0l);
    cudaGetSymbolAddress((void**)&CN1h, g_CN1h);
    cudaGetSymbolAddress((void**)&CN1l, g_CN1l);
    cudaGetSymbolAddress((void**)&CI0h, g_CI0h);
    cudaGetSymbolAddress((void**)&CI0l, g_CI0l);
    cudaGetSymbolAddress((void**)&CI1h, g_CI1h);
    cudaGetSymbolAddress((void**)&CI1l, g_CI1l);
    cudaGetSymbolAddress((void**)&deg, g_deg);
    cudaGetSymbolAddress((void**)&inv, g_inv);
    cudaGetSymbolAddress((void**)&off, g_off);
    cudaGetSymbolAddress((void**)&cur, g_cur);
    cudaGetSymbolAddress((void**)&srt, g_srt);
    cudaGetSymbolAddress((void**)&bsum, g_bsum);
    cudaGetSymbolAddress((void**)&Bhi, g_Bhi);
    cudaGetSymbolAddress((void**)&Blo, g_Blo);

    cudaFuncSetAttribute((const void*)mma_gemm2_kernel<false>,
                         cudaFuncAttributeMaxDynamicSharedMemorySize, GSMEM);
    cudaFuncSetAttribute((const void*)mma_gemm2_kernel<true>,
                         cudaFuncAttributeMaxDynamicSharedMemorySize, GSMEM);

    // order: wprep(1), xsplit(2), deg(3), merged-encode(4 <- ncu capture slot)
    wprep_all_kernel<<<(WTOTAL + 255) / 256, 256>>>(Wn, Wi, W_rel, W_root, Bhi, Blo);
    xsplit_kernel<<<(N_ALL * F_IN / 4 + 255) / 256, 256>>>(x_news, x_int, XSh, XSl);
    cudaMemsetAsync(deg, 0, NNODE * sizeof(int));
    deg_all_kernel<<<(ET + 255) / 256, 256>>>(e0d, e1d, e2d, E0, E01, ET, deg);

    // merged encode: news + interaction in one launch
    {
        GemmSeg sn = {XSh, XSl, Bhi + WOFF_ENCN, Blo + WOFF_ENCN, bn,
                      CN0h, CN0l, 768, N_NEWS, F_IN};
        GemmSeg si = {XSh + (size_t)N_NEWS * F_IN, XSl + (size_t)N_NEWS * F_IN,
                      Bhi + WOFF_ENCI, Blo + WOFF_ENCI, bi,
                      CI0h, CI0l, 512, N_INT, F_IN};
        mma_gemm2_kernel<false><<<dim3(2, YN_NEWS + YN_INT), 256, GSMEM>>>(sn, si, YN_NEWS);
    }

    // rest of CSR build
    scan_p1<<<NB_SCAN, 256>>>(deg, off, inv, bsum);
    scan_p2<<<1, 128>>>(bsum, off, ET);
    scan_p3<<<NB_SCAN, 256>>>(off, cur, bsum);
    fill_all_kernel<<<(ET + 255) / 256, 256>>>(e0s, e0d, e1s, e1d, e2s, e2d,
                                               E0, E01, ET, cur, srt);

    __nv_bfloat16* CNhs[2] = {CN0h, CN1h};
    __nv_bfloat16* CNls[2] = {CN0l, CN1l};
    __nv_bfloat16* CIhs[2] = {CI0h, CI1h};
    __nv_bfloat16* CIls[2] = {CI0l, CI1l};
    for (int l = 0; l < 2; l++) {
        __nv_bfloat16 *CNch = CNhs[l & 1], *CNcl = CNls[l & 1];
        __nv_bfloat16 *CIch = CIhs[l & 1], *CIcl = CIls[l & 1];
        __nv_bfloat16 *CNnh = CNhs[(l + 1) & 1], *CNnl = CNls[(l + 1) & 1];
        __nv_bfloat16 *CInh = CIhs[(l + 1) & 1], *CInl = CIls[(l + 1) & 1];

        agg_all_kernel<<<(NNODE * 32 + 255) / 256, 256>>>(CNch, CNcl, CIch, CIcl, off, srt, inv);

        // merged layer GEMM: news + interaction in one launch
        GemmSeg sn = {CNch, CNcl, Bhi + WOFF_LN(l), Blo + WOFF_LN(l), conv_b + (size_t)l * H,
                      CNnh, CNnl, 768, N_NEWS, 768};
        GemmSeg si = {CIch, CIcl, Bhi + WOFF_LI(l), Blo + WOFF_LI(l), conv_b + (size_t)l * H,
                      CInh, CInl, 512, N_INT, 512};
        mma_gemm2_kernel<true><<<dim3(2, YN_NEWS + YN_INT), 256, GSMEM>>>(sn, si, YN_NEWS);
    }

    out_proj_kernel<<<(N_NEWS + 31) / 32, 256>>>(CN0h, CN0l, out_W, out_b, out);
}

// round 17
// speedup vs baseline: 2.0609x; 1.1872x over previous
#include <cuda_runtime.h>
#include <cuda_bf16.h>
#include <cstdint>
#include <cstddef>

// Problem constants
#define N_NEWS 10000
#define N_INT  50000
#define N_ALL  60000
#define F_IN   768
#define H      256
#define OUTD   8
#define NNODE  70000          // [0,10000) r0-news, [10000,60000) r1-int, [60000,70000) r2-news
#define ETOT   1300000
#define NB_SCAN 69
#define YN_NEWS 157           // ceil(10000/64)
#define YN_INT  782           // ceil(50000/64)

// ---------------- device scratch ----------------
__device__ __nv_bfloat16 g_XSh[N_ALL * F_IN], g_XSl[N_ALL * F_IN];

// Activations as SPLIT bf16 (hi/lo), concatenated-K layout:
//   CN*[10000][768]: cols 0-255 X_news, 256-511 A0, 512-767 A2
//   CI*[50000][512]: cols 0-255 X_int,  256-511 A1
__device__ __nv_bfloat16 g_CN0h[N_NEWS * 768], g_CN0l[N_NEWS * 768];
__device__ __nv_bfloat16 g_CN1h[N_NEWS * 768], g_CN1l[N_NEWS * 768];
__device__ __nv_bfloat16 g_CI0h[N_INT * 512],  g_CI0l[N_INT * 512];
__device__ __nv_bfloat16 g_CI1h[N_INT * 512],  g_CI1l[N_INT * 512];

__device__ int   g_deg[NNODE];
__device__ float g_inv[NNODE];
__device__ int   g_off[NNODE + 1];
__device__ int   g_cur[NNODE];
__device__ int   g_srt[ETOT];
__device__ int   g_bsum[NB_SCAN];

// Split/transposed weights, [256 N][K] bf16, hi & lo, concatenated layout.
#define WOFF_ENCN 0
#define WOFF_ENCI 196608
#define WOFF_LN(l) (393216 + (l) * 327680)
#define WOFF_LI(l) (589824 + (l) * 327680)
#define WTOTAL 1048576
__device__ __nv_bfloat16 g_Bhi[WTOTAL];
__device__ __nv_bfloat16 g_Blo[WTOTAL];

// ================= helpers =================
__device__ __forceinline__ uint32_t smem_u32(const void* p) {
    uint32_t a;
    asm("{ .reg .u64 t; cvta.to.shared.u64 t, %1; cvt.u32.u64 %0, t; }" : "=r"(a) : "l"(p));
    return a;
}
__device__ __forceinline__ uint32_t pack_bf2(__nv_bfloat16 a, __nv_bfloat16 b) {
    return (uint32_t)__bfloat16_as_ushort(a) | ((uint32_t)__bfloat16_as_ushort(b) << 16);
}
__device__ __forceinline__ void ldm_x4(uint32_t& r0, uint32_t& r1, uint32_t& r2, uint32_t& r3,
                                       uint32_t addr) {
    asm volatile("ldmatrix.sync.aligned.m8n8.x4.shared.b16 {%0,%1,%2,%3}, [%4];"
                 : "=r"(r0), "=r"(r1), "=r"(r2), "=r"(r3) : "r"(addr));
}
__device__ __forceinline__ void mma_bf16(float* c, uint32_t a0, uint32_t a1, uint32_t a2,
                                         uint32_t a3, uint32_t b0, uint32_t b1) {
    asm volatile("mma.sync.aligned.m16n8k16.row.col.f32.bf16.bf16.f32 "
                 "{%0,%1,%2,%3}, {%4,%5,%6,%7}, {%8,%9}, {%0,%1,%2,%3};"
                 : "+f"(c[0]), "+f"(c[1]), "+f"(c[2]), "+f"(c[3])
                 : "r"(a0), "r"(a1), "r"(a2), "r"(a3), "r"(b0), "r"(b1));
}
__device__ __forceinline__ void cp16(uint32_t dst, const void* src) {
    asm volatile("cp.async.cg.shared.global [%0], [%1], 16;" :: "r"(dst), "l"(src));
}
__device__ __forceinline__ void cp16z(uint32_t dst, const void* src, int sz) {
    asm volatile("cp.async.cg.shared.global [%0], [%1], 16, %2;" :: "r"(dst), "l"(src), "r"(sz));
}
__device__ __forceinline__ void split_bf(float v, __nv_bfloat16& h, __nv_bfloat16& l) {
    h = __float2bfloat16(v);
    l = __float2bfloat16(v - __bfloat162float(h));
}

// ================= pipelined HMMA GEMM (3-term bf16 split) =================
// Two independent GEMM segments in ONE launch (blockIdx.y < yN -> seg 0).
// Per segment: C[M,0:256 of ldc] = A[M][K] @ B[K,256], A/B split bf16 hi/lo.
// Block tile 64(M) x 128(N), grid.x=2 covers N=256. 8 warps = 2m x 4n,
// warp tile 32x32 -> 3 CTAs/SM (24 warps/SM).
#define BUFSZ 30720
#define GSMEM (2 * BUFSZ)

struct GemmSeg {
    const __nv_bfloat16 *Ah, *Al, *Bh, *Bl;
    const float* bias;
    __nv_bfloat16 *Ch, *Cl;
    int ldc, M, K;
};

// A tile: 64 rows x 32 bf16 (hi+lo). Threads 0..127.
__device__ __forceinline__ void gemm_ldA(uint32_t bufb,
                                         const __nv_bfloat16* __restrict__ Ahi,
                                         const __nv_bfloat16* __restrict__ Alo,
                                         int K, int M, int row0, int tid, int k0) {
    if (tid >= 128) return;
    const int fRow = tid >> 1;
    const int fHalf = tid & 1;
    const int r = row0 + fRow;
    const int sz = (r < M) ? 16 : 0;
    const int rc = (r < M) ? r : (M - 1);
    const size_t gb = (size_t)rc * K + k0 + fHalf * 16;
    const uint32_t d = bufb + (uint32_t)(fRow * 80 + fHalf * 32);
    cp16z(d,             Ahi + gb,     sz);
    cp16z(d + 16,        Ahi + gb + 8, sz);
    cp16z(d + 5120,      Alo + gb,     sz);
    cp16z(d + 5120 + 16, Alo + gb + 8, sz);
}
// B tile: 128 rows x 32 bf16 (hi+lo). All 256 threads.
__device__ __forceinline__ void gemm_ldB(uint32_t bufb, const __nv_bfloat16* __restrict__ Bth,
                                         const __nv_bfloat16* __restrict__ Btl,
                                         int K, int col0, int tid, int k0) {
    const int fRow = tid >> 1;
    const int fHalf = tid & 1;
    const size_t gb = (size_t)(col0 + fRow) * K + k0 + fHalf * 16;
    const uint32_t d = bufb + 10240 + (uint32_t)(fRow * 80 + fHalf * 32);
    cp16(d,              Bth + gb);
    cp16(d + 16,         Bth + gb + 8);
    cp16(d + 10240,      Btl + gb);
    cp16(d + 10240 + 16, Btl + gb + 8);
}

template <bool RELU>
__global__ __launch_bounds__(256, 3) void mma_gemm2_kernel(GemmSeg s0, GemmSeg s1, int yN) {
    extern __shared__ char smem[];
    const uint32_t sb = smem_u32(smem);
    const int tid  = threadIdx.x;
    const int wid  = tid >> 5;
    const int lane = tid & 31;
    const int wm   = wid & 1;          // 2 m-warps: rows wm*32
    const int wn   = wid >> 1;         // 4 n-warps: cols wn*32
    const bool isSeg1 = ((int)blockIdx.y >= yN);
    const GemmSeg s = isSeg1 ? s1 : s0;
    const int row0 = (isSeg1 ? ((int)blockIdx.y - yN) : (int)blockIdx.y) * 64;
    const int col0 = blockIdx.x * 128;
    const int M = s.M, K = s.K, ldc = s.ldc;

    float acc[2][4][4];                 // [mt][ng*2+h][quad] = 32 regs
    #pragma unroll
    for (int i = 0; i < 2; i++)
        #pragma unroll
        for (int j = 0; j < 4; j++)
            #pragma unroll
            for (int q = 0; q < 4; q++) acc[i][j][q] = 0.f;

    const int nchunks = K >> 5;

    const uint32_t aRowOff =
        (uint32_t)(wm * 32 + ((lane >> 3) & 1) * 8 + (lane & 7)) * 80 + (lane >> 4) * 16;
    const uint32_t bRowBase =
        (uint32_t)(wn * 32 + ((lane >> 4) & 1) * 8 + (lane & 7)) * 80 + ((lane >> 3) & 1) * 16;

    gemm_ldA(sb, s.Ah, s.Al, K, M, row0, tid, 0);
    gemm_ldB(sb, s.Bh, s.Bl, K, col0, tid, 0);
    asm volatile("cp.async.commit_group;" ::: "memory");
    asm volatile("cp.async.wait_group 0;" ::: "memory");
    __syncthreads();

    for (int c = 0; c < nchunks; c++) {
        const int b = c & 1;
        const bool nxt = (c + 1) < nchunks;
        if (nxt) {
            const int k0 = (c + 1) << 5;
            gemm_ldA(sb + (b ^ 1) * BUFSZ, s.Ah, s.Al, K, M, row0, tid, k0);
            gemm_ldB(sb + (b ^ 1) * BUFSZ, s.Bh, s.Bl, K, col0, tid, k0);
            asm volatile("cp.async.commit_group;" ::: "memory");
        }

        const uint32_t aHb = sb + b * BUFSZ;
        const uint32_t aLb = aHb + 5120;
        const uint32_t bHb = aHb + 10240;
        const uint32_t bLb = aHb + 20480;
        #pragma unroll
        for (int kk = 0; kk < 2; kk++) {
            const uint32_t kOff = kk * 32;
            uint32_t ah[2][4], al[2][4];
            #pragma unroll
            for (int mt = 0; mt < 2; mt++) {
                const uint32_t roff = aRowOff + (uint32_t)(mt * 16) * 80 + kOff;
                ldm_x4(ah[mt][0], ah[mt][1], ah[mt][2], ah[mt][3], aHb + roff);
                ldm_x4(al[mt][0], al[mt][1], al[mt][2], al[mt][3], aLb + roff);
            }
            #pragma unroll
            for (int ng = 0; ng < 2; ng++) {
                const uint32_t boff = bRowBase + (uint32_t)(ng * 16) * 80 + kOff;
                uint32_t bh[4], bl[4];
                ldm_x4(bh[0], bh[1], bh[2], bh[3], bHb + boff);
                ldm_x4(bl[0], bl[1], bl[2], bl[3], bLb + boff);
                #pragma unroll
                for (int mt = 0; mt < 2; mt++)
                    #pragma unroll
                    for (int h = 0; h < 2; h++)
                        mma_bf16(acc[mt][ng * 2 + h], ah[mt][0], ah[mt][1], ah[mt][2], ah[mt][3],
                                 bh[2 * h], bh[2 * h + 1]);
                #pragma unroll
                for (int mt = 0; mt < 2; mt++)
                    #pragma unroll
                    for (int h = 0; h < 2; h++)
                        mma_bf16(acc[mt][ng * 2 + h], ah[mt][0], ah[mt][1], ah[mt][2], ah[mt][3],
                                 bl[2 * h], bl[2 * h + 1]);
                #pragma unroll
                for (int mt = 0; mt < 2; mt++)
                    #pragma unroll
                    for (int h = 0; h < 2; h++)
                        mma_bf16(acc[mt][ng * 2 + h], al[mt][0], al[mt][1], al[mt][2], al[mt][3],
                                 bh[2 * h], bh[2 * h + 1]);
            }
        }

        if (nxt) asm volatile("cp.async.wait_group 0;" ::: "memory");
        __syncthreads();
    }

    // ---- epilogue: bias + optional relu, split to bf16 hi/lo ----
    const int colBase = col0 + wn * 32 + (lane & 3) * 2;
    #pragma unroll
    for (int mt = 0; mt < 2; mt++) {
        #pragma unroll
        for (int half = 0; half < 2; half++) {
            const int r = row0 + wm * 32 + mt * 16 + (lane >> 2) + half * 8;
            if (r < M) {
                #pragma unroll
                for (int nt = 0; nt < 4; nt++) {
                    const int c = colBase + nt * 8;
                    float v0 = acc[mt][nt][2 * half];
                    float v1 = acc[mt][nt][2 * half + 1];
                    const float2 bb = *(const float2*)(s.bias + c);
                    v0 += bb.x; v1 += bb.y;
                    if (RELU) { v0 = fmaxf(v0, 0.f); v1 = fmaxf(v1, 0.f); }
                    __nv_bfloat16 h0, l0, h1, l1;
                    split_bf(v0, h0, l0);
                    split_bf(v1, h1, l1);
                    *(uint32_t*)(s.Ch + (size_t)r * ldc + c) = pack_bf2(h0, h1);
                    *(uint32_t*)(s.Cl + (size_t)r * ldc + c) = pack_bf2(l0, l1);
                }
            }
        }
    }
}

// ---------------- x pre-split ----------------
__global__ void xsplit_kernel(const float* __restrict__ xn, const float* __restrict__ xi,
                              __nv_bfloat16* __restrict__ Xh, __nv_bfloat16* __restrict__ Xl) {
    const int base = (blockIdx.x * blockDim.x + threadIdx.x) * 4;
    if (base >= N_ALL * F_IN) return;
    const float* src = (base < N_NEWS * F_IN) ? (xn + base) : (xi + (base - N_NEWS * F_IN));
    const float4 v = *(const float4*)src;
    __nv_bfloat16 hx, lx, hy, ly, hz, lz, hw, lw;
    split_bf(v.x, hx, lx); split_bf(v.y, hy, ly);
    split_bf(v.z, hz, lz); split_bf(v.w, hw, lw);
    uint2 hp, lp;
    hp.x = pack_bf2(hx, hy); hp.y = pack_bf2(hz, hw);
    lp.x = pack_bf2(lx, ly); lp.y = pack_bf2(lz, lw);
    *(uint2*)(Xh + base) = hp;
    *(uint2*)(Xl + base) = lp;
}

// ---------------- single-launch weight prep ----------------
__global__ void wprep_all_kernel(const float* __restrict__ Wn, const float* __restrict__ Wi,
                                 const float* __restrict__ W_rel, const float* __restrict__ W_root,
                                 __nv_bfloat16* __restrict__ Bhi, __nv_bfloat16* __restrict__ Blo) {
    int idx = blockIdx.x * blockDim.x + threadIdx.x;
    if (idx >= WTOTAL) return;
    const float* src;
    int base, Kdst, koff, s;
    if (idx < 196608) {
        base = WOFF_ENCN; Kdst = 768; koff = 0; s = idx; src = Wn;
    } else if (idx < 393216) {
        base = WOFF_ENCI; Kdst = 768; koff = 0; s = idx - 196608; src = Wi;
    } else {
        int t = idx - 393216;
        const int l = (t >= 327680) ? 1 : 0;
        if (l) t -= 327680;
        if (t < 196608) {
            base = WOFF_LN(l); Kdst = 768;
            const int j = t >> 16;
            s = t & 65535;
            koff = j * 256;
            src = (j == 0) ? (W_root + l * 65536)
                           : (W_rel + (l * 3 + ((j == 1) ? 0 : 2)) * 65536);
        } else {
            t -= 196608;
            base = WOFF_LI(l); Kdst = 512;
            const int j = t >> 16;
            s = t & 65535;
            koff = j * 256;
            src = (j == 0) ? (W_root + l * 65536) : (W_rel + (l * 3 + 1) * 65536);
        }
    }
    const int k = s >> 8;
    const int n = s & 255;
    const float v = src[k * 256 + n];
    __nv_bfloat16 h, l2;
    split_bf(v, h, l2);
    const size_t d = (size_t)base + (size_t)n * Kdst + koff + k;
    Bhi[d] = h;
    Blo[d] = l2;
}

// ---------------- CSR build ----------------
__global__ void deg_all_kernel(const int* __restrict__ d0, const int* __restrict__ d1,
                               const int* __restrict__ d2, int E0, int E01, int ET,
                               int* __restrict__ deg) {
    int e = blockIdx.x * blockDim.x + threadIdx.x;
    if (e >= ET) return;
    if (e < E0)       atomicAdd(&deg[d0[e]], 1);
    else if (e < E01) atomicAdd(&deg[10000 + d1[e - E0]], 1);
    else              atomicAdd(&deg[60000 + d2[e - E01]], 1);
}

__global__ __launch_bounds__(256) void scan_p1(const int* __restrict__ deg,
                                               int* __restrict__ off,
                                               float* __restrict__ inv,
                                               int* __restrict__ bsum) {
    __shared__ int ws[8];
    const int t = (int)threadIdx.x;
    const int base = (blockIdx.x * 256 + t) * 4;
    int4 d = make_int4(0, 0, 0, 0);
    if (base < NNODE) {
        d = *(const int4*)(deg + base);
        *(float4*)(inv + base) = make_float4(
            d.x > 0 ? 1.f / (float)d.x : 0.f, d.y > 0 ? 1.f / (float)d.y : 0.f,
            d.z > 0 ? 1.f / (float)d.z : 0.f, d.w > 0 ? 1.f / (float)d.w : 0.f);
    }
    const int local = d.x + d.y + d.z + d.w;
    const int lane = t & 31, w = t >> 5;
    int v = local;
    #pragma unroll
    for (int s = 1; s < 32; s <<= 1) {
        int u = __shfl_up_sync(0xFFFFFFFFu, v, s);
        if (lane >= s) v += u;
    }
    if (lane == 31) ws[w] = v;
    __syncthreads();
    if (t == 0) {
        int run = 0;
        #pragma unroll
        for (int i = 0; i < 8; i++) { int x = ws[i]; ws[i] = run; run += x; }
        bsum[blockIdx.x] = run;
    }
    __syncthreads();
    const int excl = (v - local) + ws[w];
    if (base < NNODE) {
        off[base]     = excl;
        off[base + 1] = excl + d.x;
        off[base + 2] = excl + d.x + d.y;
        off[base + 3] = excl + d.x + d.y + d.z;
    }
}

__global__ __launch_bounds__(128) void scan_p2(int* __restrict__ bsum,
                                               int* __restrict__ off, int ET) {
    __shared__ int sh[128];
    const int t = (int)threadIdx.x;
    const int v = (t < NB_SCAN) ? bsum[t] : 0;
    sh[t] = v;
    __syncthreads();
    #pragma unroll
    for (int s = 1; s < 128; s <<= 1) {
        int u = (t >= s) ? sh[t - s] : 0;
        __syncthreads();
        sh[t] += u;
        __syncthreads();
    }
    if (t < NB_SCAN) bsum[t] = sh[t] - v;
    if (t == 0) off[NNODE] = ET;
}

__global__ __launch_bounds__(256) void scan_p3(int* __restrict__ off, int* __restrict__ cur,
                                               const int* __restrict__ bsum) {
    const int base = (blockIdx.x * 256 + (int)threadIdx.x) * 4;
    if (base < NNODE) {
        const int bs = bsum[blockIdx.x];
        int4 o = *(int4*)(off + base);
        o.x += bs; o.y += bs; o.z += bs; o.w += bs;
        *(int4*)(off + base) = o;
        *(int4*)(cur + base) = o;
    }
}

__global__ void fill_all_kernel(const int* __restrict__ s0, const int* __restrict__ d0,
                                const int* __restrict__ s1, const int* __restrict__ d1,
                                const int* __restrict__ s2, const int* __restrict__ d2,
                                int E0, int E01, int ET,
                                int* __restrict__ cur, int* __restrict__ srt) {
    int e = blockIdx.x * blockDim.x + threadIdx.x;
    if (e >= ET) return;
    int di, sv;
    if (e < E0)       { di = d0[e];               sv = s0[e]; }
    else if (e < E01) { di = 10000 + d1[e - E0];  sv = s1[e - E0]; }
    else              { di = 60000 + d2[e - E01]; sv = s2[e - E01] + 10000; }
    int p = atomicAdd(&cur[di], 1);
    srt[p] = sv;
}

// ---------------- merged mean aggregation (split bf16 in/out, 2x unroll) ----------
// count = number of node-warps; remap=1 -> warps [0,10000) are r0-news nodes,
// [10000,20000) are r2-news nodes (ids 60000+i) — used for layer 1 where the
// interaction-destination aggregation (A1) is dead code.
__device__ __forceinline__ void acc8(float* a, uint4 v) {
    const __nv_bfloat162* p = (const __nv_bfloat162*)&v;
    #pragma unroll
    for (int i = 0; i < 4; i++) {
        float2 f = __bfloat1622float2(p[i]);
        a[2 * i] += f.x;
        a[2 * i + 1] += f.y;
    }
}
__device__ __forceinline__ void src_ptrs(int src, const __nv_bfloat16* CNh, const __nv_bfloat16* CNl,
                                         const __nv_bfloat16* CIh, const __nv_bfloat16* CIl,
                                         const __nv_bfloat16*& rh, const __nv_bfloat16*& rl) {
    if (src < 10000) { rh = CNh + (size_t)src * 768; rl = CNl + (size_t)src * 768; }
    else             { rh = CIh + (size_t)(src - 10000) * 512; rl = CIl + (size_t)(src - 10000) * 512; }
}

__global__ void agg_all_kernel(__nv_bfloat16* __restrict__ CNh, __nv_bfloat16* __restrict__ CNl,
                               __nv_bfloat16* __restrict__ CIh, __nv_bfloat16* __restrict__ CIl,
                               const int* __restrict__ off, const int* __restrict__ srt,
                               const float* __restrict__ inv, int count, int remap) {
    int gw = (int)((blockIdx.x * blockDim.x + threadIdx.x) >> 5);
    const int lane = threadIdx.x & 31;
    if (gw >= count) return;
    if (remap && gw >= 10000) gw += 50000;   // r2-news segment at node ids 60000+
    __nv_bfloat16 *oh, *ol;
    if (gw < 10000) {
        oh = CNh + (size_t)gw * 768 + 256; ol = CNl + (size_t)gw * 768 + 256;
    } else if (gw < 60000) {
        const int i = gw - 10000;
        oh = CIh + (size_t)i * 512 + 256; ol = CIl + (size_t)i * 512 + 256;
    } else {
        const int i = gw - 60000;
        oh = CNh + (size_t)i * 768 + 512; ol = CNl + (size_t)i * 768 + 512;
    }
    const int e0 = off[gw], e1 = off[gw + 1];
    const int co = lane * 8;
    float a[8];
    #pragma unroll
    for (int i = 0; i < 8; i++) a[i] = 0.f;
    int e = e0;
    for (; e + 2 <= e1; e += 2) {
        const int sA = __ldg(&srt[e]);
        const int sB = __ldg(&srt[e + 1]);
        const __nv_bfloat16 *rhA, *rlA, *rhB, *rlB;
        src_ptrs(sA, CNh, CNl, CIh, CIl, rhA, rlA);
        src_ptrs(sB, CNh, CNl, CIh, CIl, rhB, rlB);
        const uint4 h0 = __ldg((const uint4*)(rhA + co));
        const uint4 l0 = __ldg((const uint4*)(rlA + co));
        const uint4 h1 = __ldg((const uint4*)(rhB + co));
        const uint4 l1 = __ldg((const uint4*)(rlB + co));
        acc8(a, h0); acc8(a, l0);
        acc8(a, h1); acc8(a, l1);
    }
    if (e < e1) {
        const int sA = __ldg(&srt[e]);
        const __nv_bfloat16 *rhA, *rlA;
        src_ptrs(sA, CNh, CNl, CIh, CIl, rhA, rlA);
        acc8(a, __ldg((const uint4*)(rhA + co)));
        acc8(a, __ldg((const uint4*)(rlA + co)));
    }
    const float d = inv[gw];
    uint4 ho, lo_;
    uint32_t* hp = (uint32_t*)&ho;
    uint32_t* lp = (uint32_t*)&lo_;
    #pragma unroll
    for (int i = 0; i < 4; i++) {
        float v0 = a[2 * i] * d, v1 = a[2 * i + 1] * d;
        __nv_bfloat16 h0, l0, h1, l1;
        split_bf(v0, h0, l0);
        split_bf(v1, h1, l1);
        hp[i] = pack_bf2(h0, h1);
        lp[i] = pack_bf2(l0, l1);
    }
    *(uint4*)(oh + co) = ho;
    *(uint4*)(ol + co) = lo_;
}

// ---------------- final projection ----------------
__global__ __launch_bounds__(256) void out_proj_kernel(
    const __nv_bfloat16* __restrict__ Xh, const __nv_bfloat16* __restrict__ Xl,
    const float* __restrict__ W, const float* __restrict__ b,
    float* __restrict__ out) {
    __shared__ float sW[H * OUTD];
    for (int i = threadIdx.x; i < H * OUTD; i += 256) sW[i] = W[i];
    __syncthreads();
    const int i = blockIdx.x * 32 + ((int)threadIdx.x >> 3);
    const int o = threadIdx.x & 7;
    if (i >= N_NEWS) return;
    float s = b[o];
    const __nv_bfloat16* xh = Xh + (size_t)i * 768;
    const __nv_bfloat16* xl = Xl + (size_t)i * 768;
    #pragma unroll 8
    for (int j = 0; j < H; j++) {
        float x = __bfloat162float(xh[j]) + __bfloat162float(xl[j]);
        s += x * sW[j * OUTD + o];
    }
    out[i * OUTD + o] = s;
}

// ---------------- launch ----------------
extern "C" void kernel_launch(void* const* d_in, const int* in_sizes, int n_in,
                              void* d_out, int out_size) {
    const float* x_news = (const float*)d_in[0];
    const float* x_int  = (const float*)d_in[1];
    const float* Wn     = (const float*)d_in[2];
    const float* bn     = (const float*)d_in[3];
    const float* Wi     = (const float*)d_in[4];
    const float* bi     = (const float*)d_in[5];
    const float* W_rel  = (const float*)d_in[6];
    const float* W_root = (const float*)d_in[7];
    const float* conv_b = (const float*)d_in[8];
    const float* out_W  = (const float*)d_in[9];
    const float* out_b  = (const float*)d_in[10];
    const int* e0s = (const int*)d_in[11];
    const int* e0d = (const int*)d_in[12];
    const int* e1s = (const int*)d_in[13];
    const int* e1d = (const int*)d_in[14];
    const int* e2s = (const int*)d_in[15];
    const int* e2d = (const int*)d_in[16];
    const int E0 = in_sizes[11], E1 = in_sizes[13], E2 = in_sizes[15];
    const int E01 = E0 + E1, ET = E0 + E1 + E2;
    float* out = (float*)d_out;

    __nv_bfloat16 *XSh, *XSl, *CN0h, *CN0l, *CN1h, *CN1l, *CI0h, *CI0l, *CI1h, *CI1l, *Bhi, *Blo;
    float *inv;
    int *deg, *off, *cur, *srt, *bsum;
    cudaGetSymbolAddress((void**)&XSh, g_XSh);
    cudaGetSymbolAddress((void**)&XSl, g_XSl);
    cudaGetSymbolAddress((void**)&CN0h, g_CN0h);
    cudaGetSymbolAddress((void**)&CN0l, g_CN0l);
    cudaGetSymbolAddress((void**)&CN1h, g_CN1h);
    cudaGetSymbolAddress((void**)&CN1l, g_CN1l);
    cudaGetSymbolAddress((void**)&CI0h, g_CI0h);
    cudaGetSymbolAddress((void**)&CI0l, g_CI0l);
    cudaGetSymbolAddress((void**)&CI1h, g_CI1h);
    cudaGetSymbolAddress((void**)&CI1l, g_CI1l);
    cudaGetSymbolAddress((void**)&deg, g_deg);
    cudaGetSymbolAddress((void**)&inv, g_inv);
    cudaGetSymbolAddress((void**)&off, g_off);
    cudaGetSymbolAddress((void**)&cur, g_cur);
    cudaGetSymbolAddress((void**)&srt, g_srt);
    cudaGetSymbolAddress((void**)&bsum, g_bsum);
    cudaGetSymbolAddress((void**)&Bhi, g_Bhi);
    cudaGetSymbolAddress((void**)&Blo, g_Blo);

    cudaFuncSetAttribute((const void*)mma_gemm2_kernel<false>,
                         cudaFuncAttributeMaxDynamicSharedMemorySize, GSMEM);
    cudaFuncSetAttribute((const void*)mma_gemm2_kernel<true>,
                         cudaFuncAttributeMaxDynamicSharedMemorySize, GSMEM);

    // order: wprep(1), xsplit(2), deg(3), merged-encode(4 <- ncu capture slot)
    wprep_all_kernel<<<(WTOTAL + 255) / 256, 256>>>(Wn, Wi, W_rel, W_root, Bhi, Blo);
    xsplit_kernel<<<(N_ALL * F_IN / 4 + 255) / 256, 256>>>(x_news, x_int, XSh, XSl);
    cudaMemsetAsync(deg, 0, NNODE * sizeof(int));
    deg_all_kernel<<<(ET + 255) / 256, 256>>>(e0d, e1d, e2d, E0, E01, ET, deg);

    // merged encode: news + interaction in one launch
    {
        GemmSeg sn = {XSh, XSl, Bhi + WOFF_ENCN, Blo + WOFF_ENCN, bn,
                      CN0h, CN0l, 768, N_NEWS, F_IN};
        GemmSeg si = {XSh + (size_t)N_NEWS * F_IN, XSl + (size_t)N_NEWS * F_IN,
                      Bhi + WOFF_ENCI, Blo + WOFF_ENCI, bi,
                      CI0h, CI0l, 512, N_INT, F_IN};
        mma_gemm2_kernel<false><<<dim3(2, YN_NEWS + YN_INT), 256, GSMEM>>>(sn, si, YN_NEWS);
    }

    // rest of CSR build
    scan_p1<<<NB_SCAN, 256>>>(deg, off, inv, bsum);
    scan_p2<<<1, 128>>>(bsum, off, ET);
    scan_p3<<<NB_SCAN, 256>>>(off, cur, bsum);
    fill_all_kernel<<<(ET + 255) / 256, 256>>>(e0s, e0d, e1s, e1d, e2s, e2d,
                                               E0, E01, ET, cur, srt);

    // ---- layer 0: full (all nodes needed as layer-1 agg sources) ----
    agg_all_kernel<<<(NNODE * 32 + 255) / 256, 256>>>(
        CN0h, CN0l, CI0h, CI0l, off, srt, inv, NNODE, 0);
    {
        GemmSeg sn = {CN0h, CN0l, Bhi + WOFF_LN(0), Blo + WOFF_LN(0), conv_b,
                      CN1h, CN1l, 768, N_NEWS, 768};
        GemmSeg si = {CI0h, CI0l, Bhi + WOFF_LI(0), Blo + WOFF_LI(0), conv_b,
                      CI1h, CI1l, 512, N_INT, 512};
        mma_gemm2_kernel<true><<<dim3(2, YN_NEWS + YN_INT), 256, GSMEM>>>(sn, si, YN_NEWS);
    }

    // ---- layer 1: interaction output is DEAD (only news rows feed out_proj).
    // Skip A1 aggregation (400k edges) and the whole M=50000 interaction GEMM.
    agg_all_kernel<<<(20000 * 32 + 255) / 256, 256>>>(
        CN1h, CN1l, CI1h, CI1l, off, srt, inv, 20000, 1);
    {
        GemmSeg sn = {CN1h, CN1l, Bhi + WOFF_LN(1), Blo + WOFF_LN(1), conv_b + H,
                      CN0h, CN0l, 768, N_NEWS, 768};
        mma_gemm2_kernel<true><<<dim3(2, YN_NEWS), 256, GSMEM>>>(sn, sn, YN_NEWS);
    }

    out_proj_kernel<<<(N_NEWS + 31) / 32, 256>>>(CN0h, CN0l, out_W, out_b, out);
}